// round 7
// baseline (speedup 1.0000x reference)
#include <cuda_runtime.h>
#include <cstdint>

#define Bn 2
#define Tn 2048
#define Cn 1024
#define Hn 16
#define HDn 64
#define BTn (Bn*Tn)

// Scratch (no allocations allowed).
__device__ float g_q[Bn*Hn*Tn*HDn];
__device__ float g_k[Bn*Hn*Tn*HDn];
__device__ float g_v[Bn*Hn*Tn*HDn];
__device__ float g_y[(size_t)BTn*Cn];     // attention out (tf32-rounded)
__device__ float g_xr[(size_t)BTn*Cn];    // x, tf32-rounded
__device__ float g_wt[3*Cn*Cn];           // w_attn^T [3C, C], tf32-rounded
__device__ float g_wp[Cn*Cn];             // w_proj^T [C, C],  tf32-rounded

__device__ __forceinline__ uint32_t f2tf(float x) {
    uint32_t r;
    asm("cvt.rna.tf32.f32 %0, %1;" : "=r"(r) : "f"(x));
    return r;
}
__device__ __forceinline__ float f2tff(float x) { return __uint_as_float(f2tf(x)); }

__device__ __forceinline__ uint32_t smem_u32(const void* p) {
    uint32_t a;
    asm("{ .reg .u64 t; cvta.to.shared.u64 t, %1; cvt.u32.u64 %0, t; }"
        : "=r"(a) : "l"(p));
    return a;
}

__device__ __forceinline__ void cp16(uint32_t sdst, const void* gsrc) {
    asm volatile("cp.async.cg.shared.global [%0], [%1], 16;"
                 :: "r"(sdst), "l"(gsrc) : "memory");
}
#define CP_COMMIT() asm volatile("cp.async.commit_group;" ::: "memory")
#define CP_WAIT(n)  asm volatile("cp.async.wait_group %0;" :: "n"(n) : "memory")

// D = A@B + D, m16n8k8 tf32, A row-major, B col-major.
__device__ __forceinline__ void mma_tf32(float* d, const uint32_t* a, uint32_t b0, uint32_t b1) {
    asm volatile("mma.sync.aligned.m16n8k8.row.col.f32.tf32.tf32.f32 "
        "{%0,%1,%2,%3}, {%4,%5,%6,%7}, {%8,%9}, {%0,%1,%2,%3};\n"
        : "+f"(d[0]), "+f"(d[1]), "+f"(d[2]), "+f"(d[3])
        : "r"(a[0]), "r"(a[1]), "r"(a[2]), "r"(a[3]), "r"(b0), "r"(b1));
}

// ---------------------------------------------------------------------------
// Prep kernels.
// ---------------------------------------------------------------------------
__global__ void round_tf32(const float* __restrict__ src, float* __restrict__ dst, int n4)
{
    int i = blockIdx.x * blockDim.x + threadIdx.x;
    if (i < n4) {
        float4 v = ((const float4*)src)[i];
        ((float4*)dst)[i] = make_float4(f2tff(v.x), f2tff(v.y), f2tff(v.z), f2tff(v.w));
    }
}

__global__ void transpose_w(const float* __restrict__ src, float* __restrict__ dst,
                            int K, int N)
{
    __shared__ float t[32][33];
    int bx = blockIdx.x * 32;   // n
    int by = blockIdx.y * 32;   // k
    int x = threadIdx.x, y = threadIdx.y;
    #pragma unroll
    for (int i = 0; i < 32; i += 8)
        t[y + i][x] = src[(size_t)(by + y + i) * N + bx + x];
    __syncthreads();
    #pragma unroll
    for (int i = 0; i < 32; i += 8)
        dst[(size_t)(bx + y + i) * K + by + x] = f2tff(t[x][y + i]);
}

// ---------------------------------------------------------------------------
// tf32 mma.sync GEMM, cp.async pipeline, pre-rounded inputs (no cvt in loop).
// out[M,N] = A[M,K] @ WT[N,K]^T + bias[N].
// Block 128x128, BK=32, 256 threads = 8 warps (2m x 4n), warp tile 64x32
// (4 m-frags x 4 n-frags) -> ~120 regs, 2 CTAs/SM, 4 warps/SMSP.
// OP=0: A = g_xr, epilogue routes into g_q/g_k/g_v head-major.
// OP=1: A = g_y,  epilogue writes row-major out.
// ---------------------------------------------------------------------------
#define LDT 36
#define TILE_W (128 * LDT)                 // words per tile buffer
#define GSMEM_SZ (4 * TILE_W * 4)          // A0 A1 B0 B1 bytes

template<int OP>
__global__ __launch_bounds__(256, 2)
void gemm_cp(const float* __restrict__ A_,
             const float* __restrict__ WT,
             const float* __restrict__ bias,
             float* __restrict__ out,
             int M, int N, int K)
{
    extern __shared__ __align__(16) float smem[];
    float* Asb[2] = { smem,              smem + TILE_W };
    float* Bsb[2] = { smem + 2 * TILE_W, smem + 3 * TILE_W };

    const float* A = (OP == 0) ? g_xr : g_y;
    (void)A_;

    const int tid  = threadIdx.x;
    const int wid  = tid >> 5;
    const int lane = tid & 31;
    const int g = lane >> 2;
    const int t = lane & 3;
    const int wm = wid >> 2;       // 0..1 -> 64-row slab
    const int wn = wid & 3;        // 0..3 -> 32-col slab
    const int bm = blockIdx.y * 128;
    const int bn = blockIdx.x * 128;

    // cp.async coords: thread handles rows r0+32i (i=0..3), col chunk c4.
    const int r0 = tid >> 3;             // 0..31
    const int c4 = (tid & 7) * 4;        // 0,4,...,28
    const float* pa = A  + (size_t)(bm + r0) * K + c4;
    const float* pb = WT + (size_t)(bn + r0) * K + c4;
    const uint32_t sA[2] = { smem_u32(Asb[0]) + (uint32_t)(r0 * LDT + c4) * 4,
                             smem_u32(Asb[1]) + (uint32_t)(r0 * LDT + c4) * 4 };
    const uint32_t sB[2] = { smem_u32(Bsb[0]) + (uint32_t)(r0 * LDT + c4) * 4,
                             smem_u32(Bsb[1]) + (uint32_t)(r0 * LDT + c4) * 4 };

    float acc[4][4][4];
    #pragma unroll
    for (int mi = 0; mi < 4; mi++)
        #pragma unroll
        for (int ni = 0; ni < 4; ni++)
            #pragma unroll
            for (int e = 0; e < 4; e++) acc[mi][ni][e] = 0.f;

    const int NIT = K / 32;

    // Stage tile 0.
    #pragma unroll
    for (int i = 0; i < 4; i++) {
        cp16(sA[0] + i * 32 * LDT * 4, pa + (size_t)(32 * i) * K);
        cp16(sB[0] + i * 32 * LDT * 4, pb + (size_t)(32 * i) * K);
    }
    CP_COMMIT();

    for (int it = 0; it < NIT; it++) {
        const int cur = it & 1;
        if (it + 1 < NIT) {
            const int nxt = cur ^ 1;
            const size_t ko = (size_t)(it + 1) * 32;
            #pragma unroll
            for (int i = 0; i < 4; i++) {
                cp16(sA[nxt] + i * 32 * LDT * 4, pa + (size_t)(32 * i) * K + ko);
                cp16(sB[nxt] + i * 32 * LDT * 4, pb + (size_t)(32 * i) * K + ko);
            }
            CP_COMMIT();
            CP_WAIT(1);
        } else {
            CP_WAIT(0);
        }
        __syncthreads();

        const float* As = Asb[cur];
        const float* Bs = Bsb[cur];
        #pragma unroll
        for (int kk = 0; kk < 4; kk++) {
            uint32_t af[4][4], bf[4][2];
            #pragma unroll
            for (int mi = 0; mi < 4; mi++) {
                int row = wm * 64 + mi * 16 + g;
                af[mi][0] = __float_as_uint(As[row * LDT + kk * 8 + t]);
                af[mi][1] = __float_as_uint(As[(row + 8) * LDT + kk * 8 + t]);
                af[mi][2] = __float_as_uint(As[row * LDT + kk * 8 + t + 4]);
                af[mi][3] = __float_as_uint(As[(row + 8) * LDT + kk * 8 + t + 4]);
            }
            #pragma unroll
            for (int ni = 0; ni < 4; ni++) {
                int col = wn * 32 + ni * 8 + g;
                bf[ni][0] = __float_as_uint(Bs[col * LDT + kk * 8 + t]);
                bf[ni][1] = __float_as_uint(Bs[col * LDT + kk * 8 + t + 4]);
            }
            #pragma unroll
            for (int mi = 0; mi < 4; mi++)
                #pragma unroll
                for (int ni = 0; ni < 4; ni++)
                    mma_tf32(acc[mi][ni], af[mi], bf[ni][0], bf[ni][1]);
        }
        __syncthreads();
    }

    // Epilogue: direct stores from C-fragment layout (rows g,g+8; cols 2t,2t+1).
    #pragma unroll
    for (int mi = 0; mi < 4; mi++) {
        int m0 = bm + wm * 64 + mi * 16 + g;
        #pragma unroll
        for (int ni = 0; ni < 4; ni++) {
            int n = bn + wn * 32 + ni * 8 + 2 * t;
            float2 bia = *(const float2*)&bias[n];
            float2 v0 = make_float2(acc[mi][ni][0] + bia.x, acc[mi][ni][1] + bia.y);
            float2 v1 = make_float2(acc[mi][ni][2] + bia.x, acc[mi][ni][3] + bia.y);
            if (OP == 0) {
                int which = n >> 10;         // 0=q 1=k 2=v
                int cc = n & (Cn - 1);
                int h = cc >> 6;
                int d = cc & (HDn - 1);
                float* dst = (which == 0) ? g_q : (which == 1) ? g_k : g_v;
                int b0i = m0 >> 11, t0 = m0 & (Tn - 1);
                *(float2*)&dst[(((size_t)(b0i * Hn + h)) * Tn + t0) * HDn + d] = v0;
                int m1 = m0 + 8;
                int b1i = m1 >> 11, t1 = m1 & (Tn - 1);
                *(float2*)&dst[(((size_t)(b1i * Hn + h)) * Tn + t1) * HDn + d] = v1;
            } else {
                *(float2*)&out[(size_t)m0 * N + n] = v0;
                *(float2*)&out[(size_t)(m0 + 8) * N + n] = v1;
            }
        }
    }
}

// ---------------------------------------------------------------------------
// Flash attention on tensor cores (m16n8k8 tf32 mma). Unchanged.
// ---------------------------------------------------------------------------
#define LDK 68
#define LDV 72

__global__ __launch_bounds__(128, 4)
void attn_mma()
{
    __shared__ __align__(16) float Ks[64 * LDK];
    __shared__ __align__(16) float Vs[64 * LDV];

    const int tid  = threadIdx.x;
    const int wid  = tid >> 5;
    const int lane = tid & 31;
    const int g = lane >> 2;
    const int t = lane & 3;

    const int bh = blockIdx.x;
    const int Qi = (int)gridDim.y - 1 - (int)blockIdx.y;
    const int qbase = Qi * 64;

    const float* kg0 = g_k + (size_t)bh * Tn * HDn;
    const float* vg0 = g_v + (size_t)bh * Tn * HDn;

    uint32_t qf[8][4];
    {
        const int r0 = qbase + wid * 16 + g;
        const float* p0 = g_q + ((size_t)bh * Tn + r0) * HDn;
        const float* p1 = p0 + 8 * HDn;
        #pragma unroll
        for (int c = 0; c < 8; c++) {
            qf[c][0] = f2tf(p0[8*c + t]     * 0.125f);
            qf[c][1] = f2tf(p1[8*c + t]     * 0.125f);
            qf[c][2] = f2tf(p0[8*c + t + 4] * 0.125f);
            qf[c][3] = f2tf(p1[8*c + t + 4] * 0.125f);
        }
    }

    float o[8][4];
    #pragma unroll
    for (int d = 0; d < 8; d++) { o[d][0]=0.f; o[d][1]=0.f; o[d][2]=0.f; o[d][3]=0.f; }
    float m0 = -1e30f, m1 = -1e30f, l0 = 0.f, l1 = 0.f;

    const int row0 = qbase + wid * 16 + g;
    const int row1 = row0 + 8;

    const int nkt = Qi + 1;
    for (int kt = 0; kt < nkt; kt++) {
        __syncthreads();
        {
            const float* kg = kg0 + (size_t)kt * 64 * HDn;
            const float* vg = vg0 + (size_t)kt * 64 * HDn;
            #pragma unroll
            for (int i = 0; i < 8; i++) {
                int idx = tid + 128 * i;
                int r  = idx >> 4;
                int c4 = (idx & 15) * 4;
                float4 a = *(const float4*)(kg + r * HDn + c4);
                uint32_t* dk = (uint32_t*)&Ks[r * LDK + c4];
                dk[0]=f2tf(a.x); dk[1]=f2tf(a.y); dk[2]=f2tf(a.z); dk[3]=f2tf(a.w);
                float4 b = *(const float4*)(vg + r * HDn + c4);
                uint32_t* dv = (uint32_t*)&Vs[r * LDV + c4];
                dv[0]=f2tf(b.x); dv[1]=f2tf(b.y); dv[2]=f2tf(b.z); dv[3]=f2tf(b.w);
            }
        }
        __syncthreads();

        float s[8][4];
        #pragma unroll
        for (int n = 0; n < 8; n++) { s[n][0]=0.f; s[n][1]=0.f; s[n][2]=0.f; s[n][3]=0.f; }
        #pragma unroll
        for (int c = 0; c < 8; c++) {
            #pragma unroll
            for (int n = 0; n < 8; n++) {
                const uint32_t* kp = (const uint32_t*)&Ks[(8*n + g) * LDK + 8*c + t];
                mma_tf32(s[n], qf[c], kp[0], kp[4]);
            }
        }

        if (kt == Qi) {
            #pragma unroll
            for (int n = 0; n < 8; n++) {
                int col = kt * 64 + 8*n + 2*t;
                if (col     > row0) s[n][0] = -1e30f;
                if (col + 1 > row0) s[n][1] = -1e30f;
                if (col     > row1) s[n][2] = -1e30f;
                if (col + 1 > row1) s[n][3] = -1e30f;
            }
        }

        float mx0 = m0, mx1 = m1;
        #pragma unroll
        for (int n = 0; n < 8; n++) {
            mx0 = fmaxf(mx0, fmaxf(s[n][0], s[n][1]));
            mx1 = fmaxf(mx1, fmaxf(s[n][2], s[n][3]));
        }
        mx0 = fmaxf(mx0, __shfl_xor_sync(0xffffffff, mx0, 1));
        mx0 = fmaxf(mx0, __shfl_xor_sync(0xffffffff, mx0, 2));
        mx1 = fmaxf(mx1, __shfl_xor_sync(0xffffffff, mx1, 1));
        mx1 = fmaxf(mx1, __shfl_xor_sync(0xffffffff, mx1, 2));
        float corr0 = __expf(m0 - mx0);
        float corr1 = __expf(m1 - mx1);
        m0 = mx0; m1 = mx1;

        float rs0 = 0.f, rs1 = 0.f;
        #pragma unroll
        for (int n = 0; n < 8; n++) {
            s[n][0] = __expf(s[n][0] - m0);
            s[n][1] = __expf(s[n][1] - m0);
            s[n][2] = __expf(s[n][2] - m1);
            s[n][3] = __expf(s[n][3] - m1);
            rs0 += s[n][0] + s[n][1];
            rs1 += s[n][2] + s[n][3];
        }
        rs0 += __shfl_xor_sync(0xffffffff, rs0, 1);
        rs0 += __shfl_xor_sync(0xffffffff, rs0, 2);
        rs1 += __shfl_xor_sync(0xffffffff, rs1, 1);
        rs1 += __shfl_xor_sync(0xffffffff, rs1, 2);
        l0 = l0 * corr0 + rs0;
        l1 = l1 * corr1 + rs1;
        #pragma unroll
        for (int d = 0; d < 8; d++) {
            o[d][0] *= corr0; o[d][1] *= corr0;
            o[d][2] *= corr1; o[d][3] *= corr1;
        }

        __syncthreads();
        float* Ps = &Ks[(wid * 16) * LDK];
        #pragma unroll
        for (int n = 0; n < 8; n++) {
            *(uint2*)&Ps[g * LDK + 8*n + 2*t]       = make_uint2(f2tf(s[n][0]), f2tf(s[n][1]));
            *(uint2*)&Ps[(g + 8) * LDK + 8*n + 2*t] = make_uint2(f2tf(s[n][2]), f2tf(s[n][3]));
        }
        __syncwarp();

        #pragma unroll
        for (int c = 0; c < 8; c++) {
            uint32_t a[4];
            a[0] = *(const uint32_t*)&Ps[g * LDK + 8*c + t];
            a[1] = *(const uint32_t*)&Ps[(g + 8) * LDK + 8*c + t];
            a[2] = *(const uint32_t*)&Ps[g * LDK + 8*c + t + 4];
            a[3] = *(const uint32_t*)&Ps[(g + 8) * LDK + 8*c + t + 4];
            #pragma unroll
            for (int d = 0; d < 8; d++) {
                uint32_t b0 = *(const uint32_t*)&Vs[(8*c + t) * LDV + 8*d + g];
                uint32_t b1 = *(const uint32_t*)&Vs[(8*c + t + 4) * LDV + 8*d + g];
                mma_tf32(o[d], a, b0, b1);
            }
        }
    }

    float inv0 = 1.f / l0, inv1 = 1.f / l1;
    int b = bh / Hn, h = bh % Hn;
    float* y0 = g_y + ((size_t)b * Tn + row0) * Cn + h * HDn;
    float* y1 = g_y + ((size_t)b * Tn + row1) * Cn + h * HDn;
    #pragma unroll
    for (int d = 0; d < 8; d++) {
        *(float2*)&y0[8*d + 2*t] = make_float2(f2tff(o[d][0] * inv0), f2tff(o[d][1] * inv0));
        *(float2*)&y1[8*d + 2*t] = make_float2(f2tff(o[d][2] * inv1), f2tff(o[d][3] * inv1));
    }
}

// ---------------------------------------------------------------------------
extern "C" void kernel_launch(void* const* d_in, const int* in_sizes, int n_in,
                              void* d_out, int out_size)
{
    const float* x      = (const float*)d_in[0];
    const float* w_attn = (const float*)d_in[1];
    const float* b_attn = (const float*)d_in[2];
    const float* w_proj = (const float*)d_in[3];
    const float* b_proj = (const float*)d_in[4];
    float* out = (float*)d_out;

    cudaFuncSetAttribute(gemm_cp<0>, cudaFuncAttributeMaxDynamicSharedMemorySize, GSMEM_SZ);
    cudaFuncSetAttribute(gemm_cp<1>, cudaFuncAttributeMaxDynamicSharedMemorySize, GSMEM_SZ);

    float* xr; cudaGetSymbolAddress((void**)&xr, g_xr);
    float* wt; cudaGetSymbolAddress((void**)&wt, g_wt);
    float* wp; cudaGetSymbolAddress((void**)&wp, g_wp);

    // 0) Prep: tf32-round x; transpose+round weights.
    {
        int n4 = BTn * Cn / 4;
        round_tf32<<<(n4 + 255) / 256, 256>>>(x, xr, n4);
        dim3 blk(32, 8);
        transpose_w<<<dim3(3 * Cn / 32, Cn / 32), blk>>>(w_attn, wt, Cn, 3 * Cn);
        transpose_w<<<dim3(Cn / 32, Cn / 32), blk>>>(w_proj, wp, Cn, Cn);
    }
    // 1) QKV GEMM -> g_q/g_k/g_v (head-major).
    {
        dim3 grid(3 * Cn / 128, BTn / 128);   // (24, 32)
        gemm_cp<0><<<grid, 256, GSMEM_SZ>>>(nullptr, wt, b_attn, nullptr, BTn, 3 * Cn, Cn);
    }
    // 2) Causal flash attention -> g_y (tf32-rounded).
    {
        dim3 grid(Bn * Hn, Tn / 64);
        attn_mma<<<grid, 128>>>();
    }
    // 3) Projection GEMM: g_y @ w_proj + b_proj -> out.
    {
        dim3 grid(Cn / 128, BTn / 128);       // (8, 32)
        gemm_cp<1><<<grid, 256, GSMEM_SZ>>>(nullptr, wp, b_proj, out, BTn, Cn, Cn);
    }
}

// round 8
// speedup vs baseline: 1.3016x; 1.3016x over previous
#include <cuda_runtime.h>
#include <cstdint>

#define Bn 2
#define Tn 2048
#define Cn 1024
#define Hn 16
#define HDn 64
#define BTn (Bn*Tn)
#define K8n (Cn/8)     // 128 k8-fragments along K

// Scratch (no allocations allowed).
__device__ float g_q[Bn*Hn*Tn*HDn];
__device__ float g_k[Bn*Hn*Tn*HDn];
__device__ float g_v[Bn*Hn*Tn*HDn];
__device__ float g_y[(size_t)BTn*Cn];     // attention out (fp32)
__device__ float g_xp[(size_t)BTn*Cn];    // x, packed A-frag tf32
__device__ float g_yp[(size_t)BTn*Cn];    // y, packed A-frag tf32
__device__ float g_wt[3*Cn*Cn];           // w_attn, packed B-frag tf32
__device__ float g_wp[Cn*Cn];             // w_proj, packed B-frag tf32

__device__ __forceinline__ uint32_t f2tf(float x) {
    uint32_t r;
    asm("cvt.rna.tf32.f32 %0, %1;" : "=r"(r) : "f"(x));
    return r;
}
__device__ __forceinline__ float f2tff(float x) { return __uint_as_float(f2tf(x)); }

__device__ __forceinline__ uint32_t smem_u32(const void* p) {
    uint32_t a;
    asm("{ .reg .u64 t; cvta.to.shared.u64 t, %1; cvt.u32.u64 %0, t; }"
        : "=r"(a) : "l"(p));
    return a;
}

__device__ __forceinline__ void cp16(uint32_t sdst, const void* gsrc) {
    asm volatile("cp.async.cg.shared.global [%0], [%1], 16;"
                 :: "r"(sdst), "l"(gsrc) : "memory");
}
#define CP_COMMIT() asm volatile("cp.async.commit_group;" ::: "memory")
#define CP_WAIT(n)  asm volatile("cp.async.wait_group %0;" :: "n"(n) : "memory")

// D = A@B + D, m16n8k8 tf32, A row-major, B col-major.
__device__ __forceinline__ void mma_tf32(float* d, const uint32_t* a, uint32_t b0, uint32_t b1) {
    asm volatile("mma.sync.aligned.m16n8k8.row.col.f32.tf32.tf32.f32 "
        "{%0,%1,%2,%3}, {%4,%5,%6,%7}, {%8,%9}, {%0,%1,%2,%3};\n"
        : "+f"(d[0]), "+f"(d[1]), "+f"(d[2]), "+f"(d[3])
        : "r"(a[0]), "r"(a[1]), "r"(a[2]), "r"(a[3]), "r"(b0), "r"(b1));
}

// ---------------------------------------------------------------------------
// Prep: pack A[M,K] (row-major fp32) into A-fragment order, tf32-rounded.
// Layout: frag (m16, k8); lane (g,t) holds {A[16m16+g][8k8+t], A[..g+8][..t],
// A[..g][..t+4], A[..g+8][..t+4]} as float4 at ((m16*K8 + k8)*32 + lane)*4.
// Block: 16 rows x 256 k-cols.
// ---------------------------------------------------------------------------
__global__ __launch_bounds__(256)
void pack_a(const float* __restrict__ src, float* __restrict__ dst, int K)
{
    __shared__ float s[16][260];
    const int m16 = blockIdx.x;
    const int k0  = blockIdx.y * 256;
    const int K8  = K >> 3;
    const int tid = threadIdx.x;

    #pragma unroll
    for (int i = 0; i < 4; i++) {
        int j = tid + 256 * i;
        int r = j >> 6, c4 = (j & 63) * 4;
        *(float4*)&s[r][c4] = *(const float4*)(src + (size_t)(m16 * 16 + r) * K + k0 + c4);
    }
    __syncthreads();
    #pragma unroll
    for (int i = 0; i < 4; i++) {
        int item = tid + 256 * i;
        int k8f = item >> 5, lane = item & 31;
        int g = lane >> 2, t = lane & 3;
        float4 v = make_float4(f2tff(s[g][k8f*8 + t]),     f2tff(s[g+8][k8f*8 + t]),
                               f2tff(s[g][k8f*8 + t + 4]), f2tff(s[g+8][k8f*8 + t + 4]));
        *(float4*)(dst + ((size_t)(m16 * K8 + (k0 >> 3) + k8f) * 32 + lane) * 4) = v;
    }
}

// ---------------------------------------------------------------------------
// Prep: pack W[K,N] (row-major fp32) into B-fragment order, tf32-rounded.
// Frag (n8, k8); lane (g,t) holds {W[8k8+t][8n8+g], W[8k8+t+4][8n8+g]} as
// float2 at ((n8*K8 + k8)*32 + lane)*2.  Block: 64k x 64n tile.
// ---------------------------------------------------------------------------
__global__ __launch_bounds__(256)
void pack_b(const float* __restrict__ W, float* __restrict__ dst, int K, int N)
{
    __shared__ float s[64][68];
    const int n0 = blockIdx.x * 64;
    const int k0 = blockIdx.y * 64;
    const int K8 = K >> 3;
    const int tid = threadIdx.x;

    #pragma unroll
    for (int i = 0; i < 4; i++) {
        int j = tid + 256 * i;
        int r = j >> 4, c4 = (j & 15) * 4;
        *(float4*)&s[r][c4] = *(const float4*)(W + (size_t)(k0 + r) * N + n0 + c4);
    }
    __syncthreads();
    #pragma unroll
    for (int i = 0; i < 8; i++) {
        int item = tid + 256 * i;
        int f = item >> 5, lane = item & 31;
        int n8f = f >> 3, k8f = f & 7;
        int g = lane >> 2, t = lane & 3;
        float2 v = make_float2(f2tff(s[k8f*8 + t][n8f*8 + g]),
                               f2tff(s[k8f*8 + t + 4][n8f*8 + g]));
        *(float2*)(dst + ((size_t)(((n0 >> 3) + n8f) * K8 + (k0 >> 3) + k8f) * 32 + lane) * 2) = v;
    }
}

// ---------------------------------------------------------------------------
// tf32 mma.sync GEMM on fragment-packed inputs.
// out[M,N] = A[M,K] @ W[K,N] + bias[N], A/W pre-packed + pre-rounded.
// Block 128x128, BK=32, 128 threads = 4 warps (2m x 2n), warp tile 64x64.
// Per kk: 4x LDS.128 (A-frags) + 8x LDS.64 (B-frags) + 32 mma. cp.async
// double buffer; all fragment loads single-instruction and conflict-free.
// OP=0: A = g_xp, epilogue routes into g_q/g_k/g_v head-major.
// OP=1: A = g_yp, epilogue writes row-major out.
// ---------------------------------------------------------------------------
#define GSMEM_SZ (4 * 16384)   // A0 A1 B0 B1

template<int OP>
__global__ __launch_bounds__(128, 2)
void gemm_pk(const float* __restrict__ WTp,
             const float* __restrict__ bias,
             float* __restrict__ out,
             int M, int N, int K)
{
    extern __shared__ __align__(16) char smem[];
    const float* AP = (OP == 0) ? g_xp : g_yp;
    const int K8 = K >> 3;

    const int tid  = threadIdx.x;
    const int wid  = tid >> 5;
    const int lane = tid & 31;
    const int g = lane >> 2;
    const int t = lane & 3;
    const int wm = wid >> 1;       // 0..1 -> 64-row slab
    const int wn = wid & 1;        // 0..1 -> 64-col slab
    const int bm = blockIdx.y * 128;
    const int bn = blockIdx.x * 128;
    const int bm16 = bm >> 4;      // first m16 frag
    const int bn8  = bn >> 3;      // first n8 frag

    const uint32_t sb = smem_u32(smem);
    // smem byte offsets: A buffers at cur*16384, B at 32768 + cur*16384.

    // cp.async sources. A transfer i (i<8): m16f=i, 16B chunk tid within 2KB.
    // B transfer i: n8f = 2i + (tid>>6), 16B chunk (tid&63) within 1KB.
    const float* pa = AP  + ((size_t)bm16 * K8) * 128 + tid * 4;
    const float* pb = WTp + ((size_t)(bn8 + (tid >> 6)) * K8) * 64 + (tid & 63) * 4;

    float acc[4][8][4];
    #pragma unroll
    for (int mi = 0; mi < 4; mi++)
        #pragma unroll
        for (int ni = 0; ni < 8; ni++)
            #pragma unroll
            for (int e = 0; e < 4; e++) acc[mi][ni][e] = 0.f;

    const int NIT = K / 32;

    // Stage tile 0.
    #pragma unroll
    for (int i = 0; i < 8; i++) {
        cp16(sb + (tid + 128 * i) * 16,         pa + (size_t)i * K8 * 128);
        cp16(sb + 32768 + (tid + 128 * i) * 16, pb + (size_t)i * K8 * 128);
    }
    CP_COMMIT();

    for (int it = 0; it < NIT; it++) {
        const int cur = it & 1;
        if (it + 1 < NIT) {
            const int nxt = cur ^ 1;
            const float* pan = pa + (size_t)(it + 1) * 512;
            const float* pbn = pb + (size_t)(it + 1) * 256;
            #pragma unroll
            for (int i = 0; i < 8; i++) {
                cp16(sb + nxt * 16384 + (tid + 128 * i) * 16,         pan + (size_t)i * K8 * 128);
                cp16(sb + 32768 + nxt * 16384 + (tid + 128 * i) * 16, pbn + (size_t)i * K8 * 128);
            }
            CP_COMMIT();
            CP_WAIT(1);
        } else {
            CP_WAIT(0);
        }
        __syncthreads();

        const char* As = smem + cur * 16384;
        const char* Bs = smem + 32768 + cur * 16384;
        #pragma unroll
        for (int kk = 0; kk < 4; kk++) {
            uint4 afv[4];
            uint2 bfv[8];
            #pragma unroll
            for (int mi = 0; mi < 4; mi++)
                afv[mi] = *(const uint4*)(As + ((((wm * 4 + mi) * 4 + kk) * 32 + lane) << 4));
            #pragma unroll
            for (int ni = 0; ni < 8; ni++)
                bfv[ni] = *(const uint2*)(Bs + ((((wn * 8 + ni) * 4 + kk) * 32 + lane) << 3));
            #pragma unroll
            for (int mi = 0; mi < 4; mi++) {
                uint32_t af[4] = { afv[mi].x, afv[mi].y, afv[mi].z, afv[mi].w };
                #pragma unroll
                for (int ni = 0; ni < 8; ni++)
                    mma_tf32(acc[mi][ni], af, bfv[ni].x, bfv[ni].y);
            }
        }
        __syncthreads();
    }

    // Epilogue: direct stores from C-fragment layout (rows g,g+8; cols 2t,2t+1).
    #pragma unroll
    for (int mi = 0; mi < 4; mi++) {
        int m0 = bm + wm * 64 + mi * 16 + g;
        #pragma unroll
        for (int ni = 0; ni < 8; ni++) {
            int n = bn + wn * 64 + ni * 8 + 2 * t;
            float2 bia = *(const float2*)&bias[n];
            float2 v0 = make_float2(acc[mi][ni][0] + bia.x, acc[mi][ni][1] + bia.y);
            float2 v1 = make_float2(acc[mi][ni][2] + bia.x, acc[mi][ni][3] + bia.y);
            if (OP == 0) {
                int which = n >> 10;         // 0=q 1=k 2=v
                int cc = n & (Cn - 1);
                int h = cc >> 6;
                int d = cc & (HDn - 1);
                float* dst = (which == 0) ? g_q : (which == 1) ? g_k : g_v;
                int b0i = m0 >> 11, t0 = m0 & (Tn - 1);
                *(float2*)&dst[(((size_t)(b0i * Hn + h)) * Tn + t0) * HDn + d] = v0;
                int m1 = m0 + 8;
                int b1i = m1 >> 11, t1 = m1 & (Tn - 1);
                *(float2*)&dst[(((size_t)(b1i * Hn + h)) * Tn + t1) * HDn + d] = v1;
            } else {
                *(float2*)&out[(size_t)m0 * N + n] = v0;
                *(float2*)&out[(size_t)(m0 + 8) * N + n] = v1;
            }
        }
    }
}

// ---------------------------------------------------------------------------
// Flash attention on tensor cores (m16n8k8 tf32 mma). Round-6 version;
// epilogue writes raw fp32 (pack_a handles tf32 rounding for proj GEMM).
// ---------------------------------------------------------------------------
#define LDK 68
#define LDV 72

__global__ __launch_bounds__(128, 4)
void attn_mma()
{
    __shared__ __align__(16) float Ks[64 * LDK];
    __shared__ __align__(16) float Vs[64 * LDV];

    const int tid  = threadIdx.x;
    const int wid  = tid >> 5;
    const int lane = tid & 31;
    const int g = lane >> 2;
    const int t = lane & 3;

    const int bh = blockIdx.x;
    const int Qi = (int)gridDim.y - 1 - (int)blockIdx.y;
    const int qbase = Qi * 64;

    const float* kg0 = g_k + (size_t)bh * Tn * HDn;
    const float* vg0 = g_v + (size_t)bh * Tn * HDn;

    uint32_t qf[8][4];
    {
        const int r0 = qbase + wid * 16 + g;
        const float* p0 = g_q + ((size_t)bh * Tn + r0) * HDn;
        const float* p1 = p0 + 8 * HDn;
        #pragma unroll
        for (int c = 0; c < 8; c++) {
            qf[c][0] = f2tf(p0[8*c + t]     * 0.125f);
            qf[c][1] = f2tf(p1[8*c + t]     * 0.125f);
            qf[c][2] = f2tf(p0[8*c + t + 4] * 0.125f);
            qf[c][3] = f2tf(p1[8*c + t + 4] * 0.125f);
        }
    }

    float o[8][4];
    #pragma unroll
    for (int d = 0; d < 8; d++) { o[d][0]=0.f; o[d][1]=0.f; o[d][2]=0.f; o[d][3]=0.f; }
    float m0 = -1e30f, m1 = -1e30f, l0 = 0.f, l1 = 0.f;

    const int row0 = qbase + wid * 16 + g;
    const int row1 = row0 + 8;

    const int nkt = Qi + 1;
    for (int kt = 0; kt < nkt; kt++) {
        __syncthreads();
        {
            const float* kg = kg0 + (size_t)kt * 64 * HDn;
            const float* vg = vg0 + (size_t)kt * 64 * HDn;
            #pragma unroll
            for (int i = 0; i < 8; i++) {
                int idx = tid + 128 * i;
                int r  = idx >> 4;
                int c4 = (idx & 15) * 4;
                float4 a = *(const float4*)(kg + r * HDn + c4);
                uint32_t* dk = (uint32_t*)&Ks[r * LDK + c4];
                dk[0]=f2tf(a.x); dk[1]=f2tf(a.y); dk[2]=f2tf(a.z); dk[3]=f2tf(a.w);
                float4 b = *(const float4*)(vg + r * HDn + c4);
                uint32_t* dv = (uint32_t*)&Vs[r * LDV + c4];
                dv[0]=f2tf(b.x); dv[1]=f2tf(b.y); dv[2]=f2tf(b.z); dv[3]=f2tf(b.w);
            }
        }
        __syncthreads();

        float s[8][4];
        #pragma unroll
        for (int n = 0; n < 8; n++) { s[n][0]=0.f; s[n][1]=0.f; s[n][2]=0.f; s[n][3]=0.f; }
        #pragma unroll
        for (int c = 0; c < 8; c++) {
            #pragma unroll
            for (int n = 0; n < 8; n++) {
                const uint32_t* kp = (const uint32_t*)&Ks[(8*n + g) * LDK + 8*c + t];
                mma_tf32(s[n], qf[c], kp[0], kp[4]);
            }
        }

        if (kt == Qi) {
            #pragma unroll
            for (int n = 0; n < 8; n++) {
                int col = kt * 64 + 8*n + 2*t;
                if (col     > row0) s[n][0] = -1e30f;
                if (col + 1 > row0) s[n][1] = -1e30f;
                if (col     > row1) s[n][2] = -1e30f;
                if (col + 1 > row1) s[n][3] = -1e30f;
            }
        }

        float mx0 = m0, mx1 = m1;
        #pragma unroll
        for (int n = 0; n < 8; n++) {
            mx0 = fmaxf(mx0, fmaxf(s[n][0], s[n][1]));
            mx1 = fmaxf(mx1, fmaxf(s[n][2], s[n][3]));
        }
        mx0 = fmaxf(mx0, __shfl_xor_sync(0xffffffff, mx0, 1));
        mx0 = fmaxf(mx0, __shfl_xor_sync(0xffffffff, mx0, 2));
        mx1 = fmaxf(mx1, __shfl_xor_sync(0xffffffff, mx1, 1));
        mx1 = fmaxf(mx1, __shfl_xor_sync(0xffffffff, mx1, 2));
        float corr0 = __expf(m0 - mx0);
        float corr1 = __expf(m1 - mx1);
        m0 = mx0; m1 = mx1;

        float rs0 = 0.f, rs1 = 0.f;
        #pragma unroll
        for (int n = 0; n < 8; n++) {
            s[n][0] = __expf(s[n][0] - m0);
            s[n][1] = __expf(s[n][1] - m0);
            s[n][2] = __expf(s[n][2] - m1);
            s[n][3] = __expf(s[n][3] - m1);
            rs0 += s[n][0] + s[n][1];
            rs1 += s[n][2] + s[n][3];
        }
        rs0 += __shfl_xor_sync(0xffffffff, rs0, 1);
        rs0 += __shfl_xor_sync(0xffffffff, rs0, 2);
        rs1 += __shfl_xor_sync(0xffffffff, rs1, 1);
        rs1 += __shfl_xor_sync(0xffffffff, rs1, 2);
        l0 = l0 * corr0 + rs0;
        l1 = l1 * corr1 + rs1;
        #pragma unroll
        for (int d = 0; d < 8; d++) {
            o[d][0] *= corr0; o[d][1] *= corr0;
            o[d][2] *= corr1; o[d][3] *= corr1;
        }

        __syncthreads();
        float* Ps = &Ks[(wid * 16) * LDK];
        #pragma unroll
        for (int n = 0; n < 8; n++) {
            *(uint2*)&Ps[g * LDK + 8*n + 2*t]       = make_uint2(f2tf(s[n][0]), f2tf(s[n][1]));
            *(uint2*)&Ps[(g + 8) * LDK + 8*n + 2*t] = make_uint2(f2tf(s[n][2]), f2tf(s[n][3]));
        }
        __syncwarp();

        #pragma unroll
        for (int c = 0; c < 8; c++) {
            uint32_t a[4];
            a[0] = *(const uint32_t*)&Ps[g * LDK + 8*c + t];
            a[1] = *(const uint32_t*)&Ps[(g + 8) * LDK + 8*c + t];
            a[2] = *(const uint32_t*)&Ps[g * LDK + 8*c + t + 4];
            a[3] = *(const uint32_t*)&Ps[(g + 8) * LDK + 8*c + t + 4];
            #pragma unroll
            for (int d = 0; d < 8; d++) {
                uint32_t b0 = *(const uint32_t*)&Vs[(8*c + t) * LDV + 8*d + g];
                uint32_t b1 = *(const uint32_t*)&Vs[(8*c + t + 4) * LDV + 8*d + g];
                mma_tf32(o[d], a, b0, b1);
            }
        }
    }

    float inv0 = 1.f / l0, inv1 = 1.f / l1;
    int b = bh / Hn, h = bh % Hn;
    float* y0 = g_y + ((size_t)b * Tn + row0) * Cn + h * HDn;
    float* y1 = g_y + ((size_t)b * Tn + row1) * Cn + h * HDn;
    #pragma unroll
    for (int d = 0; d < 8; d++) {
        *(float2*)&y0[8*d + 2*t] = make_float2(o[d][0] * inv0, o[d][1] * inv0);
        *(float2*)&y1[8*d + 2*t] = make_float2(o[d][2] * inv1, o[d][3] * inv1);
    }
}

// ---------------------------------------------------------------------------
extern "C" void kernel_launch(void* const* d_in, const int* in_sizes, int n_in,
                              void* d_out, int out_size)
{
    const float* x      = (const float*)d_in[0];
    const float* w_attn = (const float*)d_in[1];
    const float* b_attn = (const float*)d_in[2];
    const float* w_proj = (const float*)d_in[3];
    const float* b_proj = (const float*)d_in[4];
    float* out = (float*)d_out;

    cudaFuncSetAttribute(gemm_pk<0>, cudaFuncAttributeMaxDynamicSharedMemorySize, GSMEM_SZ);
    cudaFuncSetAttribute(gemm_pk<1>, cudaFuncAttributeMaxDynamicSharedMemorySize, GSMEM_SZ);

    float* xp; cudaGetSymbolAddress((void**)&xp, g_xp);
    float* yp; cudaGetSymbolAddress((void**)&yp, g_yp);
    float* y;  cudaGetSymbolAddress((void**)&y,  g_y);
    float* wt; cudaGetSymbolAddress((void**)&wt, g_wt);
    float* wp; cudaGetSymbolAddress((void**)&wp, g_wp);

    // 0) Prep: pack + tf32-round x and weights into fragment layouts.
    pack_a<<<dim3(BTn / 16, Cn / 256), 256>>>(x, xp, Cn);
    pack_b<<<dim3(3 * Cn / 64, Cn / 64), 256>>>(w_attn, wt, Cn, 3 * Cn);
    pack_b<<<dim3(Cn / 64, Cn / 64), 256>>>(w_proj, wp, Cn, Cn);

    // 1) QKV GEMM -> g_q/g_k/g_v (head-major).
    {
        dim3 grid(3 * Cn / 128, BTn / 128);   // (24, 32)
        gemm_pk<0><<<grid, 128, GSMEM_SZ>>>(wt, b_attn, nullptr, BTn, 3 * Cn, Cn);
    }
    // 2) Causal flash attention -> g_y.
    {
        dim3 grid(Bn * Hn, Tn / 64);
        attn_mma<<<grid, 128>>>();
    }
    // 3) Pack y, then projection GEMM: y @ w_proj + b_proj -> out.
    pack_a<<<dim3(BTn / 16, Cn / 256), 256>>>(y, yp, Cn);
    {
        dim3 grid(Cn / 128, BTn / 128);       // (8, 32)
        gemm_pk<1><<<grid, 128, GSMEM_SZ>>>(wp, b_proj, out, BTn, Cn, Cn);
    }
}

// round 9
// speedup vs baseline: 1.3690x; 1.0518x over previous
#include <cuda_runtime.h>
#include <cstdint>

#define Bn 2
#define Tn 2048
#define Cn 1024
#define Hn 16
#define HDn 64
#define BTn (Bn*Tn)

// Scratch (no allocations allowed).
__device__ float g_q[Bn*Hn*Tn*HDn];       // head-major Q (fp32)
__device__ float g_k[Bn*Hn*Tn*HDn];
__device__ float g_v[Bn*Hn*Tn*HDn];
__device__ float g_qp[Bn*Hn*Tn*HDn];      // Q packed A-frag, *0.125, tf32
__device__ float g_kp[Bn*Hn*Tn*HDn];      // K packed B-frag (S), tf32
__device__ float g_vp[Bn*Hn*Tn*HDn];      // V packed B-frag (PV), tf32
__device__ float g_y[(size_t)BTn*Cn];     // attention out (fp32)
__device__ float g_xp[(size_t)BTn*Cn];    // x, packed A-frag tf32
__device__ float g_yp[(size_t)BTn*Cn];    // y, packed A-frag tf32
__device__ float g_wt[3*Cn*Cn];           // w_attn, packed B-frag tf32
__device__ float g_wp[Cn*Cn];             // w_proj, packed B-frag tf32

__device__ __forceinline__ uint32_t f2tf(float x) {
    uint32_t r;
    asm("cvt.rna.tf32.f32 %0, %1;" : "=r"(r) : "f"(x));
    return r;
}
__device__ __forceinline__ float f2tff(float x) { return __uint_as_float(f2tf(x)); }

__device__ __forceinline__ uint32_t smem_u32(const void* p) {
    uint32_t a;
    asm("{ .reg .u64 t; cvta.to.shared.u64 t, %1; cvt.u32.u64 %0, t; }"
        : "=r"(a) : "l"(p));
    return a;
}

__device__ __forceinline__ void cp16(uint32_t sdst, const void* gsrc) {
    asm volatile("cp.async.cg.shared.global [%0], [%1], 16;"
                 :: "r"(sdst), "l"(gsrc) : "memory");
}
#define CP_COMMIT() asm volatile("cp.async.commit_group;" ::: "memory")
#define CP_WAIT(n)  asm volatile("cp.async.wait_group %0;" :: "n"(n) : "memory")

// D = A@B + D, m16n8k8 tf32, A row-major, B col-major.
__device__ __forceinline__ void mma_tf32(float* d, const uint32_t* a, uint32_t b0, uint32_t b1) {
    asm volatile("mma.sync.aligned.m16n8k8.row.col.f32.tf32.tf32.f32 "
        "{%0,%1,%2,%3}, {%4,%5,%6,%7}, {%8,%9}, {%0,%1,%2,%3};\n"
        : "+f"(d[0]), "+f"(d[1]), "+f"(d[2]), "+f"(d[3])
        : "r"(a[0]), "r"(a[1]), "r"(a[2]), "r"(a[3]), "r"(b0), "r"(b1));
}

// ---------------------------------------------------------------------------
// Prep: pack A[M,K] (row-major fp32) into A-fragment order, tf32-rounded.
// frag (m16, k8); lane (g,t): float4 {A[16m16+g][8k8+t], A[..g+8][..t],
// A[..g][..t+4], A[..g+8][..t+4]} at ((m16*K8 + k8)*32 + lane)*4.
// ---------------------------------------------------------------------------
__global__ __launch_bounds__(256)
void pack_a(const float* __restrict__ src, float* __restrict__ dst, int K)
{
    __shared__ float s[16][260];
    const int m16 = blockIdx.x;
    const int k0  = blockIdx.y * 256;
    const int K8  = K >> 3;
    const int tid = threadIdx.x;

    #pragma unroll
    for (int i = 0; i < 4; i++) {
        int j = tid + 256 * i;
        int r = j >> 6, c4 = (j & 63) * 4;
        *(float4*)&s[r][c4] = *(const float4*)(src + (size_t)(m16 * 16 + r) * K + k0 + c4);
    }
    __syncthreads();
    #pragma unroll
    for (int i = 0; i < 4; i++) {
        int item = tid + 256 * i;
        int k8f = item >> 5, lane = item & 31;
        int g = lane >> 2, t = lane & 3;
        float4 v = make_float4(f2tff(s[g][k8f*8 + t]),     f2tff(s[g+8][k8f*8 + t]),
                               f2tff(s[g][k8f*8 + t + 4]), f2tff(s[g+8][k8f*8 + t + 4]));
        *(float4*)(dst + ((size_t)(m16 * K8 + (k0 >> 3) + k8f) * 32 + lane) * 4) = v;
    }
}

// ---------------------------------------------------------------------------
// Prep: pack W[K,N] into B-fragment order, tf32-rounded.
// frag (n8, k8); lane (g,t): float2 {W[8k8+t][8n8+g], W[8k8+t+4][8n8+g]}
// at ((n8*K8 + k8)*32 + lane)*2.
// ---------------------------------------------------------------------------
__global__ __launch_bounds__(256)
void pack_b(const float* __restrict__ W, float* __restrict__ dst, int K, int N)
{
    __shared__ float s[64][68];
    const int n0 = blockIdx.x * 64;
    const int k0 = blockIdx.y * 64;
    const int K8 = K >> 3;
    const int tid = threadIdx.x;

    #pragma unroll
    for (int i = 0; i < 4; i++) {
        int j = tid + 256 * i;
        int r = j >> 4, c4 = (j & 15) * 4;
        *(float4*)&s[r][c4] = *(const float4*)(W + (size_t)(k0 + r) * N + n0 + c4);
    }
    __syncthreads();
    #pragma unroll
    for (int i = 0; i < 8; i++) {
        int item = tid + 256 * i;
        int f = item >> 5, lane = item & 31;
        int n8f = f >> 3, k8f = f & 7;
        int g = lane >> 2, t = lane & 3;
        float2 v = make_float2(f2tff(s[k8f*8 + t][n8f*8 + g]),
                               f2tff(s[k8f*8 + t + 4][n8f*8 + g]));
        *(float2*)(dst + ((size_t)(((n0 >> 3) + n8f) * K8 + (k0 >> 3) + k8f) * 32 + lane) * 2) = v;
    }
}

// ---------------------------------------------------------------------------
// Prep: pack Q per head into A-frag order (scaled 0.125, tf32).
// Per bh: frag (m16 in [0,128), k8 in [0,8)): float4 at ((m16*8+k8)*32+lane)*4.
// Block handles (bh, 64 q-rows).
// ---------------------------------------------------------------------------
__global__ __launch_bounds__(256)
void pack_q()
{
    __shared__ float s[64][68];
    const int bh = blockIdx.x;
    const int mt = blockIdx.y;            // 64-row tile
    const int tid = threadIdx.x;
    const float* src = g_q + (size_t)bh * Tn * HDn + (size_t)mt * 64 * HDn;

    #pragma unroll
    for (int i = 0; i < 4; i++) {
        int j = tid + 256 * i;
        int r = j >> 4, c4 = (j & 15) * 4;
        *(float4*)&s[r][c4] = *(const float4*)(src + r * HDn + c4);
    }
    __syncthreads();
    float* dst = g_qp + (size_t)bh * Tn * HDn + (size_t)mt * 4096;
    #pragma unroll
    for (int i = 0; i < 4; i++) {
        int item = tid + 256 * i;            // (m16l<2b><3b k8><5b lane>)
        int m16l = item >> 8;
        int k8   = (item >> 5) & 7;
        int lane = item & 31;
        int g = lane >> 2, t = lane & 3;
        float4 v = make_float4(
            f2tff(s[m16l*16 + g    ][k8*8 + t    ] * 0.125f),
            f2tff(s[m16l*16 + g + 8][k8*8 + t    ] * 0.125f),
            f2tff(s[m16l*16 + g    ][k8*8 + t + 4] * 0.125f),
            f2tff(s[m16l*16 + g + 8][k8*8 + t + 4] * 0.125f));
        *(float4*)(dst + (size_t)item * 4) = v;
    }
}

// ---------------------------------------------------------------------------
// Prep: pack K and V per head into attention B-frag orders (tf32).
// K: frag (key8 global, dim8): float2 {K[8key8+g][8dim8+t], ..t+4} at
//    ((key8*8+dim8)*32+lane)*2  -> each 64-key tile = contiguous 16KB.
// V: frag (key8 global, dim8): float2 {V[8key8+t][8dim8+g], V[8key8+t+4][..]}
//    at ((key8*8+dim8)*32+lane)*2 -> tile contiguous 16KB.
// Block handles (bh, 64-key tile).
// ---------------------------------------------------------------------------
__global__ __launch_bounds__(256)
void pack_kv()
{
    __shared__ float sk[64][68];
    __shared__ float sv[64][68];
    const int bh = blockIdx.x;
    const int kt = blockIdx.y;
    const int tid = threadIdx.x;
    const float* ks = g_k + (size_t)bh * Tn * HDn + (size_t)kt * 64 * HDn;
    const float* vs = g_v + (size_t)bh * Tn * HDn + (size_t)kt * 64 * HDn;

    #pragma unroll
    for (int i = 0; i < 4; i++) {
        int j = tid + 256 * i;
        int r = j >> 4, c4 = (j & 15) * 4;
        *(float4*)&sk[r][c4] = *(const float4*)(ks + r * HDn + c4);
        *(float4*)&sv[r][c4] = *(const float4*)(vs + r * HDn + c4);
    }
    __syncthreads();
    float* dk = g_kp + (size_t)bh * Tn * HDn + (size_t)kt * 4096;
    float* dv = g_vp + (size_t)bh * Tn * HDn + (size_t)kt * 4096;
    #pragma unroll
    for (int i = 0; i < 8; i++) {
        int item = tid + 256 * i;            // (key8l<3b><3b dim8><5b lane>)
        int n8   = item >> 8;
        int c8   = (item >> 5) & 7;
        int lane = item & 31;
        int g = lane >> 2, t = lane & 3;
        float2 vk = make_float2(f2tff(sk[n8*8 + g][c8*8 + t]),
                                f2tff(sk[n8*8 + g][c8*8 + t + 4]));
        *(float2*)(dk + (size_t)item * 2) = vk;
        float2 vv = make_float2(f2tff(sv[n8*8 + t    ][c8*8 + g]),
                                f2tff(sv[n8*8 + t + 4][c8*8 + g]));
        *(float2*)(dv + (size_t)item * 2) = vv;
    }
}

// ---------------------------------------------------------------------------
// tf32 mma.sync GEMM on fragment-packed inputs (round-8, unchanged).
// ---------------------------------------------------------------------------
#define GSMEM_SZ (4 * 16384)

template<int OP>
__global__ __launch_bounds__(128, 2)
void gemm_pk(const float* __restrict__ WTp,
             const float* __restrict__ bias,
             float* __restrict__ out,
             int M, int N, int K)
{
    extern __shared__ __align__(16) char smem[];
    const float* AP = (OP == 0) ? g_xp : g_yp;
    const int K8 = K >> 3;

    const int tid  = threadIdx.x;
    const int wid  = tid >> 5;
    const int lane = tid & 31;
    const int g = lane >> 2;
    const int t = lane & 3;
    const int wm = wid >> 1;
    const int wn = wid & 1;
    const int bm = blockIdx.y * 128;
    const int bn = blockIdx.x * 128;
    const int bm16 = bm >> 4;
    const int bn8  = bn >> 3;

    const uint32_t sb = smem_u32(smem);
    const float* pa = AP  + ((size_t)bm16 * K8) * 128 + tid * 4;
    const float* pb = WTp + ((size_t)(bn8 + (tid >> 6)) * K8) * 64 + (tid & 63) * 4;

    float acc[4][8][4];
    #pragma unroll
    for (int mi = 0; mi < 4; mi++)
        #pragma unroll
        for (int ni = 0; ni < 8; ni++)
            #pragma unroll
            for (int e = 0; e < 4; e++) acc[mi][ni][e] = 0.f;

    const int NIT = K / 32;

    #pragma unroll
    for (int i = 0; i < 8; i++) {
        cp16(sb + (tid + 128 * i) * 16,         pa + (size_t)i * K8 * 128);
        cp16(sb + 32768 + (tid + 128 * i) * 16, pb + (size_t)i * K8 * 128);
    }
    CP_COMMIT();

    for (int it = 0; it < NIT; it++) {
        const int cur = it & 1;
        if (it + 1 < NIT) {
            const int nxt = cur ^ 1;
            const float* pan = pa + (size_t)(it + 1) * 512;
            const float* pbn = pb + (size_t)(it + 1) * 256;
            #pragma unroll
            for (int i = 0; i < 8; i++) {
                cp16(sb + nxt * 16384 + (tid + 128 * i) * 16,         pan + (size_t)i * K8 * 128);
                cp16(sb + 32768 + nxt * 16384 + (tid + 128 * i) * 16, pbn + (size_t)i * K8 * 128);
            }
            CP_COMMIT();
            CP_WAIT(1);
        } else {
            CP_WAIT(0);
        }
        __syncthreads();

        const char* As = smem + cur * 16384;
        const char* Bs = smem + 32768 + cur * 16384;
        #pragma unroll
        for (int kk = 0; kk < 4; kk++) {
            uint4 afv[4];
            uint2 bfv[8];
            #pragma unroll
            for (int mi = 0; mi < 4; mi++)
                afv[mi] = *(const uint4*)(As + ((((wm * 4 + mi) * 4 + kk) * 32 + lane) << 4));
            #pragma unroll
            for (int ni = 0; ni < 8; ni++)
                bfv[ni] = *(const uint2*)(Bs + ((((wn * 8 + ni) * 4 + kk) * 32 + lane) << 3));
            #pragma unroll
            for (int mi = 0; mi < 4; mi++) {
                uint32_t af[4] = { afv[mi].x, afv[mi].y, afv[mi].z, afv[mi].w };
                #pragma unroll
                for (int ni = 0; ni < 8; ni++)
                    mma_tf32(acc[mi][ni], af, bfv[ni].x, bfv[ni].y);
            }
        }
        __syncthreads();
    }

    #pragma unroll
    for (int mi = 0; mi < 4; mi++) {
        int m0 = bm + wm * 64 + mi * 16 + g;
        #pragma unroll
        for (int ni = 0; ni < 8; ni++) {
            int n = bn + wn * 64 + ni * 8 + 2 * t;
            float2 bia = *(const float2*)&bias[n];
            float2 v0 = make_float2(acc[mi][ni][0] + bia.x, acc[mi][ni][1] + bia.y);
            float2 v1 = make_float2(acc[mi][ni][2] + bia.x, acc[mi][ni][3] + bia.y);
            if (OP == 0) {
                int which = n >> 10;
                int cc = n & (Cn - 1);
                int h = cc >> 6;
                int d = cc & (HDn - 1);
                float* dst = (which == 0) ? g_q : (which == 1) ? g_k : g_v;
                int b0i = m0 >> 11, t0 = m0 & (Tn - 1);
                *(float2*)&dst[(((size_t)(b0i * Hn + h)) * Tn + t0) * HDn + d] = v0;
                int m1 = m0 + 8;
                int b1i = m1 >> 11, t1 = m1 & (Tn - 1);
                *(float2*)&dst[(((size_t)(b1i * Hn + h)) * Tn + t1) * HDn + d] = v1;
            } else {
                *(float2*)&out[(size_t)m0 * N + n] = v0;
                *(float2*)&out[(size_t)(m0 + 8) * N + n] = v1;
            }
        }
    }
}

// ---------------------------------------------------------------------------
// Flash attention on packed fragments. Block = 4 warps = 64 q rows.
// K/V tiles staged via cp.async (16KB each, contiguous); B-frags = LDS.64;
// Q frags = 8 LDG.128 once; P staged in dedicated SMEM region.
// ---------------------------------------------------------------------------
#define ASMEM_K 0
#define ASMEM_V 16384
#define ASMEM_P 32768
#define PS_PITCH 68
#define ASMEM_SZ (32768 + 4 * 16 * PS_PITCH * 4)

__global__ __launch_bounds__(128, 4)
void attn_pk()
{
    extern __shared__ __align__(16) char asmem[];
    const uint32_t sb = smem_u32(asmem);

    const int tid  = threadIdx.x;
    const int wid  = tid >> 5;
    const int lane = tid & 31;
    const int g = lane >> 2;
    const int t = lane & 3;

    const int bh = blockIdx.x;
    const int Qi = (int)gridDim.y - 1 - (int)blockIdx.y;   // heavy tiles first
    const int qbase = Qi * 64;

    const float* kp0 = g_kp + (size_t)bh * Tn * HDn;
    const float* vp0 = g_vp + (size_t)bh * Tn * HDn;
    float* Ps = (float*)(asmem + ASMEM_P) + wid * 16 * PS_PITCH;

    // Q fragments: 8 LDG.128 from packed layout.
    uint4 qv[8];
    {
        const int m16 = Qi * 4 + wid;
        const float* qsrc = g_qp + (size_t)bh * Tn * HDn;
        #pragma unroll
        for (int c = 0; c < 8; c++)
            qv[c] = *(const uint4*)(qsrc + ((size_t)(m16 * 8 + c) * 32 + lane) * 4);
    }

    float o[8][4];
    #pragma unroll
    for (int d = 0; d < 8; d++) { o[d][0]=0.f; o[d][1]=0.f; o[d][2]=0.f; o[d][3]=0.f; }
    float m0 = -1e30f, m1 = -1e30f, l0 = 0.f, l1 = 0.f;

    const int row0 = qbase + wid * 16 + g;
    const int row1 = row0 + 8;

    const int nkt = Qi + 1;
    for (int kt = 0; kt < nkt; kt++) {
        __syncthreads();   // all warps done reading previous K/V tiles
        {
            const float* ksrc = kp0 + (size_t)kt * 4096 + tid * 4;
            const float* vsrc = vp0 + (size_t)kt * 4096 + tid * 4;
            #pragma unroll
            for (int i = 0; i < 8; i++) {
                cp16(sb + ASMEM_K + (tid + 128 * i) * 16, ksrc + (size_t)i * 512);
                cp16(sb + ASMEM_V + (tid + 128 * i) * 16, vsrc + (size_t)i * 512);
            }
        }
        CP_COMMIT();
        CP_WAIT(0);
        __syncthreads();

        // S = Q @ K^T : B-frag (key chunk n, dim chunk c) = one LDS.64.
        const uint2* Ksf = (const uint2*)(asmem + ASMEM_K);
        float s[8][4];
        #pragma unroll
        for (int n = 0; n < 8; n++) { s[n][0]=0.f; s[n][1]=0.f; s[n][2]=0.f; s[n][3]=0.f; }
        #pragma unroll
        for (int c = 0; c < 8; c++) {
            uint32_t af[4] = { qv[c].x, qv[c].y, qv[c].z, qv[c].w };
            #pragma unroll
            for (int n = 0; n < 8; n++) {
                uint2 b = Ksf[((n * 8 + c) << 5) + lane];
                mma_tf32(s[n], af, b.x, b.y);
            }
        }

        // Causal mask on diagonal tile.
        if (kt == Qi) {
            #pragma unroll
            for (int n = 0; n < 8; n++) {
                int col = kt * 64 + 8*n + 2*t;
                if (col     > row0) s[n][0] = -1e30f;
                if (col + 1 > row0) s[n][1] = -1e30f;
                if (col     > row1) s[n][2] = -1e30f;
                if (col + 1 > row1) s[n][3] = -1e30f;
            }
        }

        // Online softmax (rows g and g+8).
        float mx0 = m0, mx1 = m1;
        #pragma unroll
        for (int n = 0; n < 8; n++) {
            mx0 = fmaxf(mx0, fmaxf(s[n][0], s[n][1]));
            mx1 = fmaxf(mx1, fmaxf(s[n][2], s[n][3]));
        }
        mx0 = fmaxf(mx0, __shfl_xor_sync(0xffffffff, mx0, 1));
        mx0 = fmaxf(mx0, __shfl_xor_sync(0xffffffff, mx0, 2));
        mx1 = fmaxf(mx1, __shfl_xor_sync(0xffffffff, mx1, 1));
        mx1 = fmaxf(mx1, __shfl_xor_sync(0xffffffff, mx1, 2));
        float corr0 = __expf(m0 - mx0);
        float corr1 = __expf(m1 - mx1);
        m0 = mx0; m1 = mx1;

        float rs0 = 0.f, rs1 = 0.f;
        #pragma unroll
        for (int n = 0; n < 8; n++) {
            s[n][0] = __expf(s[n][0] - m0);
            s[n][1] = __expf(s[n][1] - m0);
            s[n][2] = __expf(s[n][2] - m1);
            s[n][3] = __expf(s[n][3] - m1);
            rs0 += s[n][0] + s[n][1];
            rs1 += s[n][2] + s[n][3];
        }
        rs0 += __shfl_xor_sync(0xffffffff, rs0, 1);
        rs0 += __shfl_xor_sync(0xffffffff, rs0, 2);
        rs1 += __shfl_xor_sync(0xffffffff, rs1, 1);
        rs1 += __shfl_xor_sync(0xffffffff, rs1, 2);
        l0 = l0 * corr0 + rs0;
        l1 = l1 * corr1 + rs1;
        #pragma unroll
        for (int d = 0; d < 8; d++) {
            o[d][0] *= corr0; o[d][1] *= corr0;
            o[d][2] *= corr1; o[d][3] *= corr1;
        }

        // Stage P (tf32) into per-warp region (no block sync needed).
        #pragma unroll
        for (int n = 0; n < 8; n++) {
            *(uint2*)&Ps[g * PS_PITCH + 8*n + 2*t]       = make_uint2(f2tf(s[n][0]), f2tf(s[n][1]));
            *(uint2*)&Ps[(g + 8) * PS_PITCH + 8*n + 2*t] = make_uint2(f2tf(s[n][2]), f2tf(s[n][3]));
        }
        __syncwarp();

        // O += P @ V : B-frag (key chunk c, dim chunk d) = one LDS.64.
        const uint2* Vsf = (const uint2*)(asmem + ASMEM_V);
        #pragma unroll
        for (int c = 0; c < 8; c++) {
            uint32_t a[4];
            a[0] = *(const uint32_t*)&Ps[g * PS_PITCH + 8*c + t];
            a[1] = *(const uint32_t*)&Ps[(g + 8) * PS_PITCH + 8*c + t];
            a[2] = *(const uint32_t*)&Ps[g * PS_PITCH + 8*c + t + 4];
            a[3] = *(const uint32_t*)&Ps[(g + 8) * PS_PITCH + 8*c + t + 4];
            #pragma unroll
            for (int d = 0; d < 8; d++) {
                uint2 b = Vsf[((c * 8 + d) << 5) + lane];
                mma_tf32(o[d], a, b.x, b.y);
            }
        }
        __syncwarp();   // P reads done before next-iter overwrite
    }

    // Epilogue: O /= l, write head-major slice of g_y (fp32).
    float inv0 = 1.f / l0, inv1 = 1.f / l1;
    int b = bh / Hn, h = bh % Hn;
    float* y0 = g_y + ((size_t)b * Tn + row0) * Cn + h * HDn;
    float* y1 = g_y + ((size_t)b * Tn + row1) * Cn + h * HDn;
    #pragma unroll
    for (int d = 0; d < 8; d++) {
        *(float2*)&y0[8*d + 2*t] = make_float2(o[d][0] * inv0, o[d][1] * inv0);
        *(float2*)&y1[8*d + 2*t] = make_float2(o[d][2] * inv1, o[d][3] * inv1);
    }
}

// ---------------------------------------------------------------------------
extern "C" void kernel_launch(void* const* d_in, const int* in_sizes, int n_in,
                              void* d_out, int out_size)
{
    const float* x      = (const float*)d_in[0];
    const float* w_attn = (const float*)d_in[1];
    const float* b_attn = (const float*)d_in[2];
    const float* w_proj = (const float*)d_in[3];
    const float* b_proj = (const float*)d_in[4];
    float* out = (float*)d_out;

    cudaFuncSetAttribute(gemm_pk<0>, cudaFuncAttributeMaxDynamicSharedMemorySize, GSMEM_SZ);
    cudaFuncSetAttribute(gemm_pk<1>, cudaFuncAttributeMaxDynamicSharedMemorySize, GSMEM_SZ);
    cudaFuncSetAttribute(attn_pk,    cudaFuncAttributeMaxDynamicSharedMemorySize, ASMEM_SZ);

    float* xp; cudaGetSymbolAddress((void**)&xp, g_xp);
    float* yp; cudaGetSymbolAddress((void**)&yp, g_yp);
    float* y;  cudaGetSymbolAddress((void**)&y,  g_y);
    float* wt; cudaGetSymbolAddress((void**)&wt, g_wt);
    float* wp; cudaGetSymbolAddress((void**)&wp, g_wp);

    // 0) Prep: pack + tf32-round x and weights into fragment layouts.
    pack_a<<<dim3(BTn / 16, Cn / 256), 256>>>(x, xp, Cn);
    pack_b<<<dim3(3 * Cn / 64, Cn / 64), 256>>>(w_attn, wt, Cn, 3 * Cn);
    pack_b<<<dim3(Cn / 64, Cn / 64), 256>>>(w_proj, wp, Cn, Cn);

    // 1) QKV GEMM -> g_q/g_k/g_v (head-major fp32).
    {
        dim3 grid(3 * Cn / 128, BTn / 128);   // (24, 32)
        gemm_pk<0><<<grid, 128, GSMEM_SZ>>>(wt, b_attn, nullptr, BTn, 3 * Cn, Cn);
    }
    // 1b) Pack Q/K/V into attention fragment layouts.
    pack_q<<<dim3(Bn * Hn, Tn / 64), 256>>>();
    pack_kv<<<dim3(Bn * Hn, Tn / 64), 256>>>();

    // 2) Causal flash attention -> g_y.
    {
        dim3 grid(Bn * Hn, Tn / 64);
        attn_pk<<<grid, 128, ASMEM_SZ>>>();
    }
    // 3) Pack y, then projection GEMM: y @ w_proj + b_proj -> out.
    pack_a<<<dim3(BTn / 16, Cn / 256), 256>>>(y, yp, Cn);
    {
        dim3 grid(Cn / 128, BTn / 128);       // (8, 32)
        gemm_pk<1><<<grid, 128, GSMEM_SZ>>>(wp, b_proj, out, BTn, Cn, Cn);
    }
}

// round 10
// speedup vs baseline: 1.4240x; 1.0401x over previous
#include <cuda_runtime.h>
#include <cstdint>

#define Bn 2
#define Tn 2048
#define Cn 1024
#define Hn 16
#define HDn 64
#define BTn (Bn*Tn)

// Scratch (no allocations allowed) — all in packed fragment layouts.
__device__ float g_qp[Bn*Hn*Tn*HDn];      // Q packed A-frag (per head), *0.125, tf32
__device__ float g_kp[Bn*Hn*Tn*HDn];      // K packed B-frag (S), tf32
__device__ float g_vp[Bn*Hn*Tn*HDn];      // V packed B-frag (PV), tf32
__device__ float g_xp[(size_t)BTn*Cn];    // x, packed A-frag tf32
__device__ float g_yp[(size_t)BTn*Cn];    // attn out, packed A-frag tf32
__device__ float g_wt[3*Cn*Cn];           // w_attn, packed B-frag tf32
__device__ float g_wp[Cn*Cn];             // w_proj, packed B-frag tf32

__device__ __forceinline__ uint32_t f2tf(float x) {
    uint32_t r;
    asm("cvt.rna.tf32.f32 %0, %1;" : "=r"(r) : "f"(x));
    return r;
}
__device__ __forceinline__ float f2tff(float x) { return __uint_as_float(f2tf(x)); }

__device__ __forceinline__ uint32_t smem_u32(const void* p) {
    uint32_t a;
    asm("{ .reg .u64 t; cvta.to.shared.u64 t, %1; cvt.u32.u64 %0, t; }"
        : "=r"(a) : "l"(p));
    return a;
}

__device__ __forceinline__ void cp16(uint32_t sdst, const void* gsrc) {
    asm volatile("cp.async.cg.shared.global [%0], [%1], 16;"
                 :: "r"(sdst), "l"(gsrc) : "memory");
}
#define CP_COMMIT() asm volatile("cp.async.commit_group;" ::: "memory")
#define CP_WAIT(n)  asm volatile("cp.async.wait_group %0;" :: "n"(n) : "memory")

// D = A@B + D, m16n8k8 tf32, A row-major, B col-major.
__device__ __forceinline__ void mma_tf32(float* d, const uint32_t* a, uint32_t b0, uint32_t b1) {
    asm volatile("mma.sync.aligned.m16n8k8.row.col.f32.tf32.tf32.f32 "
        "{%0,%1,%2,%3}, {%4,%5,%6,%7}, {%8,%9}, {%0,%1,%2,%3};\n"
        : "+f"(d[0]), "+f"(d[1]), "+f"(d[2]), "+f"(d[3])
        : "r"(a[0]), "r"(a[1]), "r"(a[2]), "r"(a[3]), "r"(b0), "r"(b1));
}

// ---------------------------------------------------------------------------
// Prep: pack A[M,K] into A-fragment order, tf32-rounded.
// frag (m16, k8); lane (g,t): float4 {A[16m16+g][8k8+t], A[..g+8][..t],
// A[..g][..t+4], A[..g+8][..t+4]} at ((m16*K8 + k8)*32 + lane)*4.
// ---------------------------------------------------------------------------
__global__ __launch_bounds__(256)
void pack_a(const float* __restrict__ src, float* __restrict__ dst, int K)
{
    __shared__ float s[16][260];
    const int m16 = blockIdx.x;
    const int k0  = blockIdx.y * 256;
    const int K8  = K >> 3;
    const int tid = threadIdx.x;

    #pragma unroll
    for (int i = 0; i < 4; i++) {
        int j = tid + 256 * i;
        int r = j >> 6, c4 = (j & 63) * 4;
        *(float4*)&s[r][c4] = *(const float4*)(src + (size_t)(m16 * 16 + r) * K + k0 + c4);
    }
    __syncthreads();
    #pragma unroll
    for (int i = 0; i < 4; i++) {
        int item = tid + 256 * i;
        int k8f = item >> 5, lane = item & 31;
        int g = lane >> 2, t = lane & 3;
        float4 v = make_float4(f2tff(s[g][k8f*8 + t]),     f2tff(s[g+8][k8f*8 + t]),
                               f2tff(s[g][k8f*8 + t + 4]), f2tff(s[g+8][k8f*8 + t + 4]));
        *(float4*)(dst + ((size_t)(m16 * K8 + (k0 >> 3) + k8f) * 32 + lane) * 4) = v;
    }
}

// ---------------------------------------------------------------------------
// Prep: pack W[K,N] into B-fragment order, tf32-rounded.
// frag (n8, k8); lane (g,t): float2 {W[8k8+t][8n8+g], W[8k8+t+4][8n8+g]}
// at ((n8*K8 + k8)*32 + lane)*2.
// ---------------------------------------------------------------------------
__global__ __launch_bounds__(256)
void pack_b(const float* __restrict__ W, float* __restrict__ dst, int K, int N)
{
    __shared__ float s[64][68];
    const int n0 = blockIdx.x * 64;
    const int k0 = blockIdx.y * 64;
    const int K8 = K >> 3;
    const int tid = threadIdx.x;

    #pragma unroll
    for (int i = 0; i < 4; i++) {
        int j = tid + 256 * i;
        int r = j >> 4, c4 = (j & 15) * 4;
        *(float4*)&s[r][c4] = *(const float4*)(W + (size_t)(k0 + r) * N + n0 + c4);
    }
    __syncthreads();
    #pragma unroll
    for (int i = 0; i < 8; i++) {
        int item = tid + 256 * i;
        int f = item >> 5, lane = item & 31;
        int n8f = f >> 3, k8f = f & 7;
        int g = lane >> 2, t = lane & 3;
        float2 v = make_float2(f2tff(s[k8f*8 + t][n8f*8 + g]),
                               f2tff(s[k8f*8 + t + 4][n8f*8 + g]));
        *(float2*)(dst + ((size_t)(((n0 >> 3) + n8f) * K8 + (k0 >> 3) + k8f) * 32 + lane) * 2) = v;
    }
}

// ---------------------------------------------------------------------------
// tf32 mma.sync GEMM on fragment-packed inputs.
// OP=0: epilogue stages tile in SMEM and writes g_qp/g_kp/g_vp packed.
// OP=1: A = g_yp, epilogue writes row-major out directly from registers.
// ---------------------------------------------------------------------------
#define EPITCH 132
#define GSMEM0_SZ (128 * EPITCH * 4)     // 67584 >= 4*16384
#define GSMEM1_SZ (4 * 16384)

template<int OP>
__global__ __launch_bounds__(128, 2)
void gemm_pk(const float* __restrict__ WTp,
             const float* __restrict__ bias,
             float* __restrict__ out,
             int M, int N, int K)
{
    extern __shared__ __align__(16) char smem[];
    const float* AP = (OP == 0) ? g_xp : g_yp;
    const int K8 = K >> 3;

    const int tid  = threadIdx.x;
    const int wid  = tid >> 5;
    const int lane = tid & 31;
    const int g = lane >> 2;
    const int t = lane & 3;
    const int wm = wid >> 1;
    const int wn = wid & 1;
    const int bm = blockIdx.y * 128;
    const int bn = blockIdx.x * 128;
    const int bm16 = bm >> 4;
    const int bn8  = bn >> 3;

    const uint32_t sb = smem_u32(smem);
    const float* pa = AP  + ((size_t)bm16 * K8) * 128 + tid * 4;
    const float* pb = WTp + ((size_t)(bn8 + (tid >> 6)) * K8) * 64 + (tid & 63) * 4;

    float acc[4][8][4];
    #pragma unroll
    for (int mi = 0; mi < 4; mi++)
        #pragma unroll
        for (int ni = 0; ni < 8; ni++)
            #pragma unroll
            for (int e = 0; e < 4; e++) acc[mi][ni][e] = 0.f;

    const int NIT = K / 32;

    #pragma unroll
    for (int i = 0; i < 8; i++) {
        cp16(sb + (tid + 128 * i) * 16,         pa + (size_t)i * K8 * 128);
        cp16(sb + 32768 + (tid + 128 * i) * 16, pb + (size_t)i * K8 * 128);
    }
    CP_COMMIT();

    for (int it = 0; it < NIT; it++) {
        const int cur = it & 1;
        if (it + 1 < NIT) {
            const int nxt = cur ^ 1;
            const float* pan = pa + (size_t)(it + 1) * 512;
            const float* pbn = pb + (size_t)(it + 1) * 256;
            #pragma unroll
            for (int i = 0; i < 8; i++) {
                cp16(sb + nxt * 16384 + (tid + 128 * i) * 16,         pan + (size_t)i * K8 * 128);
                cp16(sb + 32768 + nxt * 16384 + (tid + 128 * i) * 16, pbn + (size_t)i * K8 * 128);
            }
            CP_COMMIT();
            CP_WAIT(1);
        } else {
            CP_WAIT(0);
        }
        __syncthreads();

        const char* As = smem + cur * 16384;
        const char* Bs = smem + 32768 + cur * 16384;
        #pragma unroll
        for (int kk = 0; kk < 4; kk++) {
            uint4 afv[4];
            uint2 bfv[8];
            #pragma unroll
            for (int mi = 0; mi < 4; mi++)
                afv[mi] = *(const uint4*)(As + ((((wm * 4 + mi) * 4 + kk) * 32 + lane) << 4));
            #pragma unroll
            for (int ni = 0; ni < 8; ni++)
                bfv[ni] = *(const uint2*)(Bs + ((((wn * 8 + ni) * 4 + kk) * 32 + lane) << 3));
            #pragma unroll
            for (int mi = 0; mi < 4; mi++) {
                uint32_t af[4] = { afv[mi].x, afv[mi].y, afv[mi].z, afv[mi].w };
                #pragma unroll
                for (int ni = 0; ni < 8; ni++)
                    mma_tf32(acc[mi][ni], af, bfv[ni].x, bfv[ni].y);
            }
        }
        __syncthreads();
    }

    if (OP == 1) {
        // Direct register epilogue: row-major out + bias.
        #pragma unroll
        for (int mi = 0; mi < 4; mi++) {
            int m0 = bm + wm * 64 + mi * 16 + g;
            #pragma unroll
            for (int ni = 0; ni < 8; ni++) {
                int n = bn + wn * 64 + ni * 8 + 2 * t;
                float2 bia = *(const float2*)&bias[n];
                *(float2*)&out[(size_t)m0 * N + n] =
                    make_float2(acc[mi][ni][0] + bia.x, acc[mi][ni][1] + bia.y);
                *(float2*)&out[(size_t)(m0 + 8) * N + n] =
                    make_float2(acc[mi][ni][2] + bia.x, acc[mi][ni][3] + bia.y);
            }
        }
        return;
    }

    // OP==0: stage tile (+bias) in SMEM, then write packed Q/K/V fragments.
    float* S = (float*)smem;
    #pragma unroll
    for (int mi = 0; mi < 4; mi++) {
        int r0 = wm * 64 + mi * 16 + g;
        #pragma unroll
        for (int ni = 0; ni < 8; ni++) {
            int c = wn * 64 + ni * 8 + 2 * t;
            float2 bia = *(const float2*)&bias[bn + c];
            *(float2*)&S[r0 * EPITCH + c] =
                make_float2(acc[mi][ni][0] + bia.x, acc[mi][ni][1] + bia.y);
            *(float2*)&S[(r0 + 8) * EPITCH + c] =
                make_float2(acc[mi][ni][2] + bia.x, acc[mi][ni][3] + bia.y);
        }
    }
    __syncthreads();

    const int which = bn >> 10;          // 0=q 1=k 2=v
    const int h0 = (bn & (Cn - 1)) >> 6; // first head in this tile
    const int b = bm >> 11;
    const int tloc = bm & (Tn - 1);

    if (which == 0) {
        // Q: A-frag per head, scaled 0.125. 2 heads x 64 frags; warp: 32 units.
        #pragma unroll 4
        for (int i = 0; i < 32; i++) {
            int u = wid * 32 + i;
            int hh = u >> 6, fi = u & 63;
            int m16l = fi >> 3, k8 = fi & 7;
            int col = hh * 64 + k8 * 8;
            float4 v = make_float4(
                f2tff(S[(m16l * 16 + g    ) * EPITCH + col + t    ] * 0.125f),
                f2tff(S[(m16l * 16 + g + 8) * EPITCH + col + t    ] * 0.125f),
                f2tff(S[(m16l * 16 + g    ) * EPITCH + col + t + 4] * 0.125f),
                f2tff(S[(m16l * 16 + g + 8) * EPITCH + col + t + 4] * 0.125f));
            int bh = b * Hn + h0 + hh;
            int m16 = (tloc >> 4) + m16l;
            *(float4*)(g_qp + (size_t)bh * Tn * HDn
                       + ((size_t)(m16 * 8 + k8) * 32 + lane) * 4) = v;
        }
    } else {
        // K/V: B-frag per head. 2 heads x 128 frags; warp: 64 units.
        float* base = (which == 1) ? g_kp : g_vp;
        #pragma unroll 4
        for (int i = 0; i < 64; i++) {
            int u = wid * 64 + i;
            int hh = u >> 7, fi = u & 127;
            int key8l = fi >> 3, dim8 = fi & 7;
            int col = hh * 64 + dim8 * 8;
            float2 v;
            if (which == 1)
                v = make_float2(f2tff(S[(key8l * 8 + g) * EPITCH + col + t]),
                                f2tff(S[(key8l * 8 + g) * EPITCH + col + t + 4]));
            else
                v = make_float2(f2tff(S[(key8l * 8 + t    ) * EPITCH + col + g]),
                                f2tff(S[(key8l * 8 + t + 4) * EPITCH + col + g]));
            int bh = b * Hn + h0 + hh;
            int key8 = (tloc >> 3) + key8l;
            *(float2*)(base + (size_t)bh * Tn * HDn
                       + ((size_t)(key8 * 8 + dim8) * 32 + lane) * 2) = v;
        }
    }
}

// ---------------------------------------------------------------------------
// Flash attention on packed fragments; epilogue writes g_yp (A-frag, tf32).
// ---------------------------------------------------------------------------
#define ASMEM_K 0
#define ASMEM_V 16384
#define ASMEM_P 32768
#define PS_PITCH 68
#define ASMEM_SZ (32768 + 4 * 16 * PS_PITCH * 4)

__global__ __launch_bounds__(128, 4)
void attn_pk()
{
    extern __shared__ __align__(16) char asmem[];
    const uint32_t sb = smem_u32(asmem);

    const int tid  = threadIdx.x;
    const int wid  = tid >> 5;
    const int lane = tid & 31;
    const int g = lane >> 2;
    const int t = lane & 3;

    const int bh = blockIdx.x;
    const int Qi = (int)gridDim.y - 1 - (int)blockIdx.y;   // heavy tiles first
    const int qbase = Qi * 64;

    const float* kp0 = g_kp + (size_t)bh * Tn * HDn;
    const float* vp0 = g_vp + (size_t)bh * Tn * HDn;
    float* Ps = (float*)(asmem + ASMEM_P) + wid * 16 * PS_PITCH;

    uint4 qv[8];
    {
        const int m16 = Qi * 4 + wid;
        const float* qsrc = g_qp + (size_t)bh * Tn * HDn;
        #pragma unroll
        for (int c = 0; c < 8; c++)
            qv[c] = *(const uint4*)(qsrc + ((size_t)(m16 * 8 + c) * 32 + lane) * 4);
    }

    float o[8][4];
    #pragma unroll
    for (int d = 0; d < 8; d++) { o[d][0]=0.f; o[d][1]=0.f; o[d][2]=0.f; o[d][3]=0.f; }
    float m0 = -1e30f, m1 = -1e30f, l0 = 0.f, l1 = 0.f;

    const int row0 = qbase + wid * 16 + g;
    const int row1 = row0 + 8;

    const int nkt = Qi + 1;
    for (int kt = 0; kt < nkt; kt++) {
        __syncthreads();
        {
            const float* ksrc = kp0 + (size_t)kt * 4096 + tid * 4;
            const float* vsrc = vp0 + (size_t)kt * 4096 + tid * 4;
            #pragma unroll
            for (int i = 0; i < 8; i++) {
                cp16(sb + ASMEM_K + (tid + 128 * i) * 16, ksrc + (size_t)i * 512);
                cp16(sb + ASMEM_V + (tid + 128 * i) * 16, vsrc + (size_t)i * 512);
            }
        }
        CP_COMMIT();
        CP_WAIT(0);
        __syncthreads();

        const uint2* Ksf = (const uint2*)(asmem + ASMEM_K);
        float s[8][4];
        #pragma unroll
        for (int n = 0; n < 8; n++) { s[n][0]=0.f; s[n][1]=0.f; s[n][2]=0.f; s[n][3]=0.f; }
        #pragma unroll
        for (int c = 0; c < 8; c++) {
            uint32_t af[4] = { qv[c].x, qv[c].y, qv[c].z, qv[c].w };
            #pragma unroll
            for (int n = 0; n < 8; n++) {
                uint2 b = Ksf[((n * 8 + c) << 5) + lane];
                mma_tf32(s[n], af, b.x, b.y);
            }
        }

        if (kt == Qi) {
            #pragma unroll
            for (int n = 0; n < 8; n++) {
                int col = kt * 64 + 8*n + 2*t;
                if (col     > row0) s[n][0] = -1e30f;
                if (col + 1 > row0) s[n][1] = -1e30f;
                if (col     > row1) s[n][2] = -1e30f;
                if (col + 1 > row1) s[n][3] = -1e30f;
            }
        }

        float mx0 = m0, mx1 = m1;
        #pragma unroll
        for (int n = 0; n < 8; n++) {
            mx0 = fmaxf(mx0, fmaxf(s[n][0], s[n][1]));
            mx1 = fmaxf(mx1, fmaxf(s[n][2], s[n][3]));
        }
        mx0 = fmaxf(mx0, __shfl_xor_sync(0xffffffff, mx0, 1));
        mx0 = fmaxf(mx0, __shfl_xor_sync(0xffffffff, mx0, 2));
        mx1 = fmaxf(mx1, __shfl_xor_sync(0xffffffff, mx1, 1));
        mx1 = fmaxf(mx1, __shfl_xor_sync(0xffffffff, mx1, 2));
        float corr0 = __expf(m0 - mx0);
        float corr1 = __expf(m1 - mx1);
        m0 = mx0; m1 = mx1;

        float rs0 = 0.f, rs1 = 0.f;
        #pragma unroll
        for (int n = 0; n < 8; n++) {
            s[n][0] = __expf(s[n][0] - m0);
            s[n][1] = __expf(s[n][1] - m0);
            s[n][2] = __expf(s[n][2] - m1);
            s[n][3] = __expf(s[n][3] - m1);
            rs0 += s[n][0] + s[n][1];
            rs1 += s[n][2] + s[n][3];
        }
        rs0 += __shfl_xor_sync(0xffffffff, rs0, 1);
        rs0 += __shfl_xor_sync(0xffffffff, rs0, 2);
        rs1 += __shfl_xor_sync(0xffffffff, rs1, 1);
        rs1 += __shfl_xor_sync(0xffffffff, rs1, 2);
        l0 = l0 * corr0 + rs0;
        l1 = l1 * corr1 + rs1;
        #pragma unroll
        for (int d = 0; d < 8; d++) {
            o[d][0] *= corr0; o[d][1] *= corr0;
            o[d][2] *= corr1; o[d][3] *= corr1;
        }

        #pragma unroll
        for (int n = 0; n < 8; n++) {
            *(uint2*)&Ps[g * PS_PITCH + 8*n + 2*t]       = make_uint2(f2tf(s[n][0]), f2tf(s[n][1]));
            *(uint2*)&Ps[(g + 8) * PS_PITCH + 8*n + 2*t] = make_uint2(f2tf(s[n][2]), f2tf(s[n][3]));
        }
        __syncwarp();

        const uint2* Vsf = (const uint2*)(asmem + ASMEM_V);
        #pragma unroll
        for (int c = 0; c < 8; c++) {
            uint32_t a[4];
            a[0] = *(const uint32_t*)&Ps[g * PS_PITCH + 8*c + t];
            a[1] = *(const uint32_t*)&Ps[(g + 8) * PS_PITCH + 8*c + t];
            a[2] = *(const uint32_t*)&Ps[g * PS_PITCH + 8*c + t + 4];
            a[3] = *(const uint32_t*)&Ps[(g + 8) * PS_PITCH + 8*c + t + 4];
            #pragma unroll
            for (int d = 0; d < 8; d++) {
                uint2 b = Vsf[((c * 8 + d) << 5) + lane];
                mma_tf32(o[d], a, b.x, b.y);
            }
        }
        __syncwarp();
    }

    // Epilogue: O /= l -> per-warp SMEM bounce -> g_yp in A-frag layout.
    float inv0 = 1.f / l0, inv1 = 1.f / l1;
    #pragma unroll
    for (int d = 0; d < 8; d++) {
        *(float2*)&Ps[g * PS_PITCH + 8*d + 2*t] =
            make_float2(o[d][0] * inv0, o[d][1] * inv0);
        *(float2*)&Ps[(g + 8) * PS_PITCH + 8*d + 2*t] =
            make_float2(o[d][2] * inv1, o[d][3] * inv1);
    }
    __syncwarp();

    const int b = bh / Hn, h = bh % Hn;
    const int m16 = (b * Tn + qbase + wid * 16) >> 4;   // global row group
    #pragma unroll
    for (int d = 0; d < 8; d++) {
        float4 v = make_float4(
            f2tff(Ps[g * PS_PITCH + 8*d + t]),
            f2tff(Ps[(g + 8) * PS_PITCH + 8*d + t]),
            f2tff(Ps[g * PS_PITCH + 8*d + t + 4]),
            f2tff(Ps[(g + 8) * PS_PITCH + 8*d + t + 4]));
        int k8 = h * 8 + d;                              // K8 = Cn/8 = 128
        *(float4*)(g_yp + ((size_t)(m16 * 128 + k8) * 32 + lane) * 4) = v;
    }
}

// ---------------------------------------------------------------------------
extern "C" void kernel_launch(void* const* d_in, const int* in_sizes, int n_in,
                              void* d_out, int out_size)
{
    const float* x      = (const float*)d_in[0];
    const float* w_attn = (const float*)d_in[1];
    const float* b_attn = (const float*)d_in[2];
    const float* w_proj = (const float*)d_in[3];
    const float* b_proj = (const float*)d_in[4];
    float* out = (float*)d_out;

    cudaFuncSetAttribute(gemm_pk<0>, cudaFuncAttributeMaxDynamicSharedMemorySize, GSMEM0_SZ);
    cudaFuncSetAttribute(gemm_pk<1>, cudaFuncAttributeMaxDynamicSharedMemorySize, GSMEM1_SZ);
    cudaFuncSetAttribute(attn_pk,    cudaFuncAttributeMaxDynamicSharedMemorySize, ASMEM_SZ);

    float* xp; cudaGetSymbolAddress((void**)&xp, g_xp);
    float* wt; cudaGetSymbolAddress((void**)&wt, g_wt);
    float* wp; cudaGetSymbolAddress((void**)&wp, g_wp);

    // 0) Prep: pack + tf32-round x and weights into fragment layouts.
    pack_a<<<dim3(BTn / 16, Cn / 256), 256>>>(x, xp, Cn);
    pack_b<<<dim3(3 * Cn / 64, Cn / 64), 256>>>(w_attn, wt, Cn, 3 * Cn);
    pack_b<<<dim3(Cn / 64, Cn / 64), 256>>>(w_proj, wp, Cn, Cn);

    // 1) QKV GEMM -> g_qp/g_kp/g_vp (attention fragment layouts, fused pack).
    {
        dim3 grid(3 * Cn / 128, BTn / 128);   // (24, 32)
        gemm_pk<0><<<grid, 128, GSMEM0_SZ>>>(wt, b_attn, nullptr, BTn, 3 * Cn, Cn);
    }
    // 2) Causal flash attention -> g_yp (proj A-frag layout, fused pack).
    {
        dim3 grid(Bn * Hn, Tn / 64);
        attn_pk<<<grid, 128, ASMEM_SZ>>>();
    }
    // 3) Projection GEMM: g_yp @ w_proj + b_proj -> out.
    {
        dim3 grid(Cn / 128, BTn / 128);       // (8, 32)
        gemm_pk<1><<<grid, 128, GSMEM1_SZ>>>(wp, b_proj, out, BTn, Cn, Cn);
    }
}

// round 11
// speedup vs baseline: 2.5713x; 1.8057x over previous
#include <cuda_runtime.h>
#include <cuda_fp16.h>
#include <cstdint>

#define Bn 2
#define Tn 2048
#define Cn 1024
#define Hn 16
#define HDn 64
#define BTn (Bn*Tn)

// Scratch (no allocations allowed) — all fp16 in packed fragment layouts.
__device__ __half g_qp[Bn*Hn*Tn*HDn];     // Q A-frag (per head), *0.125
__device__ __half g_kp[Bn*Hn*Tn*HDn];     // K B-frag (S)
__device__ __half g_vp[Bn*Hn*Tn*HDn];     // V B-frag (PV)
__device__ __half g_xp[(size_t)BTn*Cn];   // x, A-frag
__device__ __half g_yp[(size_t)BTn*Cn];   // attn out, A-frag
__device__ __half g_wt[3*Cn*Cn];          // w_attn, B-frag
__device__ __half g_wp[Cn*Cn];            // w_proj, B-frag

__device__ __forceinline__ uint32_t h2pk(float a, float b) {
    __half2 h = __floats2half2_rn(a, b);
    return *(uint32_t*)&h;
}

__device__ __forceinline__ uint32_t smem_u32(const void* p) {
    uint32_t a;
    asm("{ .reg .u64 t; cvta.to.shared.u64 t, %1; cvt.u32.u64 %0, t; }"
        : "=r"(a) : "l"(p));
    return a;
}

__device__ __forceinline__ void cp16(uint32_t sdst, const void* gsrc) {
    asm volatile("cp.async.cg.shared.global [%0], [%1], 16;"
                 :: "r"(sdst), "l"(gsrc) : "memory");
}
#define CP_COMMIT() asm volatile("cp.async.commit_group;" ::: "memory")
#define CP_WAIT(n)  asm volatile("cp.async.wait_group %0;" :: "n"(n) : "memory")

// D = A@B + D, m16n8k16 fp16 inputs, fp32 accum. A row-major, B col-major.
__device__ __forceinline__ void mma_f16(float* d, const uint32_t* a, uint32_t b0, uint32_t b1) {
    asm volatile("mma.sync.aligned.m16n8k16.row.col.f32.f16.f16.f32 "
        "{%0,%1,%2,%3}, {%4,%5,%6,%7}, {%8,%9}, {%0,%1,%2,%3};\n"
        : "+f"(d[0]), "+f"(d[1]), "+f"(d[2]), "+f"(d[3])
        : "r"(a[0]), "r"(a[1]), "r"(a[2]), "r"(a[3]), "r"(b0), "r"(b1));
}

// ---------------------------------------------------------------------------
// Prep: pack A[M,K] fp32 -> fp16 A-frag order (m16n8k16).
// frag (m16, k16); lane (g,t) uint4: {h2(A[16m16+g][16k16+2t..+1]),
// h2(A[..g+8][..]), h2(A[..g][..+8,+9]), h2(A[..g+8][..+8,+9])}.
// ---------------------------------------------------------------------------
__global__ __launch_bounds__(256)
void pack_a(const float* __restrict__ src, __half* __restrict__ dst, int K)
{
    __shared__ float s[16][260];
    const int m16 = blockIdx.x;
    const int k0  = blockIdx.y * 256;
    const int K16 = K >> 4;
    const int tid = threadIdx.x;

    #pragma unroll
    for (int i = 0; i < 4; i++) {
        int j = tid + 256 * i;
        int r = j >> 6, c4 = (j & 63) * 4;
        *(float4*)&s[r][c4] = *(const float4*)(src + (size_t)(m16 * 16 + r) * K + k0 + c4);
    }
    __syncthreads();
    uint4* d4 = (uint4*)dst;
    #pragma unroll
    for (int i = 0; i < 2; i++) {
        int item = tid + 256 * i;            // 512 items: 16 k16 x 32 lanes
        int k16f = item >> 5, lane = item & 31;
        int g = lane >> 2, t = lane & 3;
        int c = k16f * 16 + 2 * t;
        uint4 v;
        v.x = h2pk(s[g    ][c],     s[g    ][c + 1]);
        v.y = h2pk(s[g + 8][c],     s[g + 8][c + 1]);
        v.z = h2pk(s[g    ][c + 8], s[g    ][c + 9]);
        v.w = h2pk(s[g + 8][c + 8], s[g + 8][c + 9]);
        d4[(size_t)(m16 * K16 + (k0 >> 4) + k16f) * 32 + lane] = v;
    }
}

// ---------------------------------------------------------------------------
// Prep: pack W[K,N] fp32 -> fp16 B-frag order (m16n8k16).
// frag (n8, k16); lane (g,t) uint2: {h2(W[16k16+2t][8n8+g], W[..+1][..]),
// h2(W[..+2t+8][..], W[..+2t+9][..])}.
// ---------------------------------------------------------------------------
__global__ __launch_bounds__(256)
void pack_b(const float* __restrict__ W, __half* __restrict__ dst, int K, int N)
{
    __shared__ float s[64][68];
    const int n0 = blockIdx.x * 64;
    const int k0 = blockIdx.y * 64;
    const int K16 = K >> 4;
    const int tid = threadIdx.x;

    #pragma unroll
    for (int i = 0; i < 4; i++) {
        int j = tid + 256 * i;
        int r = j >> 4, c4 = (j & 15) * 4;
        *(float4*)&s[r][c4] = *(const float4*)(W + (size_t)(k0 + r) * N + n0 + c4);
    }
    __syncthreads();
    uint2* d2 = (uint2*)dst;
    #pragma unroll
    for (int i = 0; i < 4; i++) {
        int item = tid + 256 * i;            // 1024 items: 8 n8 x 4 k16 x 32
        int f = item >> 5, lane = item & 31;
        int n8f = f >> 2, k16f = f & 3;
        int g = lane >> 2, t = lane & 3;
        int r = k16f * 16 + 2 * t, c = n8f * 8 + g;
        uint2 v;
        v.x = h2pk(s[r    ][c], s[r + 1][c]);
        v.y = h2pk(s[r + 8][c], s[r + 9][c]);
        d2[(size_t)(((n0 >> 3) + n8f) * K16 + (k0 >> 4) + k16f) * 32 + lane] = v;
    }
}

// ---------------------------------------------------------------------------
// fp16 mma.sync GEMM on fragment-packed inputs. BK=64, NIT=K/64.
// Block 128x128, 4 warps (2m x 2n), warp tile 64x64 (4 m16 x 8 n8).
// OP=0: epilogue stages fp32 tile in SMEM, writes g_qp/g_kp/g_vp packed fp16.
// OP=1: A = g_yp, epilogue writes fp32 row-major out directly.
// ---------------------------------------------------------------------------
#define EPITCH 132
#define GSMEM0_SZ (128 * EPITCH * 4)     // 67584 >= 65536 (pipeline buffers)
#define GSMEM1_SZ (4 * 16384)

template<int OP>
__global__ __launch_bounds__(128, 2)
void gemm_pk(const __half* __restrict__ WTp,
             const float* __restrict__ bias,
             float* __restrict__ out,
             int M, int N, int K)
{
    extern __shared__ __align__(16) char smem[];
    const __half* AP = (OP == 0) ? g_xp : g_yp;
    const int K16 = K >> 4;

    const int tid  = threadIdx.x;
    const int wid  = tid >> 5;
    const int lane = tid & 31;
    const int g = lane >> 2;
    const int t = lane & 3;
    const int wm = wid >> 1;
    const int wn = wid & 1;
    const int bm = blockIdx.y * 128;
    const int bn = blockIdx.x * 128;
    const int bm16 = bm >> 4;
    const int bn8  = bn >> 3;

    const uint32_t sb = smem_u32(smem);
    // A: frag 512B; per m16 chunk (4 k16) = 2KB. B: frag 256B; per n8 = 1KB.
    const char* pa = (const char*)AP + ((size_t)bm16 * K16) * 512 + (size_t)tid * 16;
    const char* pb = (const char*)WTp + ((size_t)(bn8 + (tid >> 6)) * K16) * 256
                     + (size_t)(tid & 63) * 16;
    const uint32_t adst = sb + tid * 16;
    const uint32_t bdst = sb + 32768 + (tid >> 6) * 1024 + (tid & 63) * 16;

    float acc[4][8][4];
    #pragma unroll
    for (int mi = 0; mi < 4; mi++)
        #pragma unroll
        for (int ni = 0; ni < 8; ni++)
            #pragma unroll
            for (int e = 0; e < 4; e++) acc[mi][ni][e] = 0.f;

    const int NIT = K / 64;

    #pragma unroll
    for (int i = 0; i < 8; i++) {
        cp16(adst + i * 2048, pa + (size_t)i * K16 * 512);
        cp16(bdst + i * 2048, pb + (size_t)(2 * i) * K16 * 256);
    }
    CP_COMMIT();

    for (int it = 0; it < NIT; it++) {
        const int cur = it & 1;
        if (it + 1 < NIT) {
            const int nxt = cur ^ 1;
            const size_t ao = (size_t)(it + 1) * 2048;
            const size_t bo = (size_t)(it + 1) * 1024;
            #pragma unroll
            for (int i = 0; i < 8; i++) {
                cp16(adst + nxt * 16384 + i * 2048, pa + (size_t)i * K16 * 512 + ao);
                cp16(bdst + nxt * 16384 + i * 2048, pb + (size_t)(2 * i) * K16 * 256 + bo);
            }
            CP_COMMIT();
            CP_WAIT(1);
        } else {
            CP_WAIT(0);
        }
        __syncthreads();

        const char* As = smem + cur * 16384;
        const char* Bs = smem + 32768 + cur * 16384;
        #pragma unroll
        for (int kk = 0; kk < 4; kk++) {
            uint4 afv[4];
            uint2 bfv[8];
            #pragma unroll
            for (int mi = 0; mi < 4; mi++)
                afv[mi] = *(const uint4*)(As + ((((wm * 4 + mi) * 4 + kk) * 32 + lane) << 4));
            #pragma unroll
            for (int ni = 0; ni < 8; ni++)
                bfv[ni] = *(const uint2*)(Bs + ((((wn * 8 + ni) * 4 + kk) * 32 + lane) << 3));
            #pragma unroll
            for (int mi = 0; mi < 4; mi++) {
                uint32_t af[4] = { afv[mi].x, afv[mi].y, afv[mi].z, afv[mi].w };
                #pragma unroll
                for (int ni = 0; ni < 8; ni++)
                    mma_f16(acc[mi][ni], af, bfv[ni].x, bfv[ni].y);
            }
        }
        __syncthreads();
    }

    if (OP == 1) {
        #pragma unroll
        for (int mi = 0; mi < 4; mi++) {
            int m0 = bm + wm * 64 + mi * 16 + g;
            #pragma unroll
            for (int ni = 0; ni < 8; ni++) {
                int n = bn + wn * 64 + ni * 8 + 2 * t;
                float2 bia = *(const float2*)&bias[n];
                *(float2*)&out[(size_t)m0 * N + n] =
                    make_float2(acc[mi][ni][0] + bia.x, acc[mi][ni][1] + bia.y);
                *(float2*)&out[(size_t)(m0 + 8) * N + n] =
                    make_float2(acc[mi][ni][2] + bia.x, acc[mi][ni][3] + bia.y);
            }
        }
        return;
    }

    // OP==0: stage tile (+bias) fp32 in SMEM, then write packed fp16 Q/K/V.
    float* S = (float*)smem;
    #pragma unroll
    for (int mi = 0; mi < 4; mi++) {
        int r0 = wm * 64 + mi * 16 + g;
        #pragma unroll
        for (int ni = 0; ni < 8; ni++) {
            int c = wn * 64 + ni * 8 + 2 * t;
            float2 bia = *(const float2*)&bias[bn + c];
            *(float2*)&S[r0 * EPITCH + c] =
                make_float2(acc[mi][ni][0] + bia.x, acc[mi][ni][1] + bia.y);
            *(float2*)&S[(r0 + 8) * EPITCH + c] =
                make_float2(acc[mi][ni][2] + bia.x, acc[mi][ni][3] + bia.y);
        }
    }
    __syncthreads();

    const int which = bn >> 10;          // 0=q 1=k 2=v
    const int h0 = (bn & (Cn - 1)) >> 6;
    const int b = bm >> 11;
    const int tloc = bm & (Tn - 1);

    if (which == 0) {
        // Q A-frags: 2 heads x 8 m16l x 4 k16 = 64 units; 16/warp.
        uint4* q4 = (uint4*)g_qp;
        #pragma unroll 4
        for (int i = 0; i < 16; i++) {
            int u = wid * 16 + i;
            int hh = u >> 5, fi = u & 31;
            int m16l = fi >> 2, k16 = fi & 3;
            int col = hh * 64 + k16 * 16 + 2 * t;
            int rg = (m16l * 16 + g) * EPITCH, rg8 = rg + 8 * EPITCH;
            uint4 v;
            v.x = h2pk(S[rg  + col    ] * 0.125f, S[rg  + col + 1] * 0.125f);
            v.y = h2pk(S[rg8 + col    ] * 0.125f, S[rg8 + col + 1] * 0.125f);
            v.z = h2pk(S[rg  + col + 8] * 0.125f, S[rg  + col + 9] * 0.125f);
            v.w = h2pk(S[rg8 + col + 8] * 0.125f, S[rg8 + col + 9] * 0.125f);
            int bh = b * Hn + h0 + hh;
            int m16 = (tloc >> 4) + m16l;
            q4[(size_t)bh * 16384 + (m16 * 4 + k16) * 32 + lane] = v;
        }
    } else if (which == 1) {
        // K B-frags (S): 2 heads x 16 key8l x 4 dim16 = 128 units; 32/warp.
        uint2* k2 = (uint2*)g_kp;
        #pragma unroll 4
        for (int i = 0; i < 32; i++) {
            int u = wid * 32 + i;
            int hh = u >> 6, fi = u & 63;
            int key8l = fi >> 2, dim16 = fi & 3;
            int col = hh * 64 + dim16 * 16 + 2 * t;
            int r = (key8l * 8 + g) * EPITCH;
            uint2 v;
            v.x = h2pk(S[r + col    ], S[r + col + 1]);
            v.y = h2pk(S[r + col + 8], S[r + col + 9]);
            int bh = b * Hn + h0 + hh;
            int key8 = (tloc >> 3) + key8l;
            k2[(size_t)bh * 32768 + (key8 * 4 + dim16) * 32 + lane] = v;
        }
    } else {
        // V B-frags (PV): 2 heads x 8 key16l x 8 dim8 = 128 units; 32/warp.
        uint2* v2 = (uint2*)g_vp;
        #pragma unroll 4
        for (int i = 0; i < 32; i++) {
            int u = wid * 32 + i;
            int hh = u >> 6, fi = u & 63;
            int key16l = fi >> 3, dim8 = fi & 7;
            int col = hh * 64 + dim8 * 8 + g;
            int r = (key16l * 16 + 2 * t) * EPITCH;
            uint2 v;
            v.x = h2pk(S[r + col],               S[r + EPITCH + col]);
            v.y = h2pk(S[r + 8 * EPITCH + col],  S[r + 9 * EPITCH + col]);
            int bh = b * Hn + h0 + hh;
            int key16 = (tloc >> 4) + key16l;
            v2[(size_t)bh * 32768 + (key16 * 8 + dim8) * 32 + lane] = v;
        }
    }
}

// ---------------------------------------------------------------------------
// Flash attention, fp16 m16n8k16. Block = 4 warps = 64 q rows.
// K/V tiles 8KB each via cp.async; P staged as half2 (pitch 36, conflict-free).
// Epilogue writes g_yp in proj A-frag layout.
// ---------------------------------------------------------------------------
#define ASMEM_K 0
#define ASMEM_V 8192
#define ASMEM_P 16384
#define PSP 36                                   // half2 pitch per row
#define ASMEM_SZ (16384 + 4 * 16 * PSP * 4)      // 25600

__global__ __launch_bounds__(128, 4)
void attn_pk()
{
    extern __shared__ __align__(16) char asmem[];
    const uint32_t sb = smem_u32(asmem);

    const int tid  = threadIdx.x;
    const int wid  = tid >> 5;
    const int lane = tid & 31;
    const int g = lane >> 2;
    const int t = lane & 3;

    const int bh = blockIdx.x;
    const int Qi = (int)gridDim.y - 1 - (int)blockIdx.y;   // heavy tiles first
    const int qbase = Qi * 64;

    const char* kbase = (const char*)g_kp + (size_t)bh * Tn * HDn * 2;
    const char* vbase = (const char*)g_vp + (size_t)bh * Tn * HDn * 2;
    uint32_t* Ps2 = (uint32_t*)(asmem + ASMEM_P) + wid * 16 * PSP;

    // Q fragments: 4 LDG.128 from packed layout.
    uint4 qv[4];
    {
        const uint4* qsrc = (const uint4*)g_qp + (size_t)bh * 16384;
        const int m16 = Qi * 4 + wid;
        #pragma unroll
        for (int c = 0; c < 4; c++)
            qv[c] = qsrc[(m16 * 4 + c) * 32 + lane];
    }

    float o[8][4];
    #pragma unroll
    for (int d = 0; d < 8; d++) { o[d][0]=0.f; o[d][1]=0.f; o[d][2]=0.f; o[d][3]=0.f; }
    float m0 = -1e30f, m1 = -1e30f, l0 = 0.f, l1 = 0.f;

    const int row0 = qbase + wid * 16 + g;
    const int row1 = row0 + 8;

    const int nkt = Qi + 1;
    for (int kt = 0; kt < nkt; kt++) {
        __syncthreads();
        {
            const char* ks = kbase + (size_t)kt * 8192 + tid * 16;
            const char* vs = vbase + (size_t)kt * 8192 + tid * 16;
            #pragma unroll
            for (int i = 0; i < 4; i++) {
                cp16(sb + ASMEM_K + tid * 16 + i * 2048, ks + (size_t)i * 2048);
                cp16(sb + ASMEM_V + tid * 16 + i * 2048, vs + (size_t)i * 2048);
            }
        }
        CP_COMMIT();
        CP_WAIT(0);
        __syncthreads();

        // S = Q @ K^T : 4 k16 steps x 8 key8 frags.
        const uint2* Ksf = (const uint2*)(asmem + ASMEM_K);
        float s[8][4];
        #pragma unroll
        for (int n = 0; n < 8; n++) { s[n][0]=0.f; s[n][1]=0.f; s[n][2]=0.f; s[n][3]=0.f; }
        #pragma unroll
        for (int c = 0; c < 4; c++) {
            uint32_t af[4] = { qv[c].x, qv[c].y, qv[c].z, qv[c].w };
            #pragma unroll
            for (int n = 0; n < 8; n++) {
                uint2 b = Ksf[((n * 4 + c) << 5) + lane];
                mma_f16(s[n], af, b.x, b.y);
            }
        }

        if (kt == Qi) {
            #pragma unroll
            for (int n = 0; n < 8; n++) {
                int col = kt * 64 + 8*n + 2*t;
                if (col     > row0) s[n][0] = -1e30f;
                if (col + 1 > row0) s[n][1] = -1e30f;
                if (col     > row1) s[n][2] = -1e30f;
                if (col + 1 > row1) s[n][3] = -1e30f;
            }
        }

        float mx0 = m0, mx1 = m1;
        #pragma unroll
        for (int n = 0; n < 8; n++) {
            mx0 = fmaxf(mx0, fmaxf(s[n][0], s[n][1]));
            mx1 = fmaxf(mx1, fmaxf(s[n][2], s[n][3]));
        }
        mx0 = fmaxf(mx0, __shfl_xor_sync(0xffffffff, mx0, 1));
        mx0 = fmaxf(mx0, __shfl_xor_sync(0xffffffff, mx0, 2));
        mx1 = fmaxf(mx1, __shfl_xor_sync(0xffffffff, mx1, 1));
        mx1 = fmaxf(mx1, __shfl_xor_sync(0xffffffff, mx1, 2));
        float corr0 = __expf(m0 - mx0);
        float corr1 = __expf(m1 - mx1);
        m0 = mx0; m1 = mx1;

        float rs0 = 0.f, rs1 = 0.f;
        #pragma unroll
        for (int n = 0; n < 8; n++) {
            s[n][0] = __expf(s[n][0] - m0);
            s[n][1] = __expf(s[n][1] - m0);
            s[n][2] = __expf(s[n][2] - m1);
            s[n][3] = __expf(s[n][3] - m1);
            rs0 += s[n][0] + s[n][1];
            rs1 += s[n][2] + s[n][3];
        }
        rs0 += __shfl_xor_sync(0xffffffff, rs0, 1);
        rs0 += __shfl_xor_sync(0xffffffff, rs0, 2);
        rs1 += __shfl_xor_sync(0xffffffff, rs1, 1);
        rs1 += __shfl_xor_sync(0xffffffff, rs1, 2);
        l0 = l0 * corr0 + rs0;
        l1 = l1 * corr1 + rs1;
        #pragma unroll
        for (int d = 0; d < 8; d++) {
            o[d][0] *= corr0; o[d][1] *= corr0;
            o[d][2] *= corr1; o[d][3] *= corr1;
        }

        // Stage P as half2 (per-warp region).
        #pragma unroll
        for (int n = 0; n < 8; n++) {
            Ps2[g * PSP + 4*n + t]       = h2pk(s[n][0], s[n][1]);
            Ps2[(g + 8) * PSP + 4*n + t] = h2pk(s[n][2], s[n][3]);
        }
        __syncwarp();

        // O += P @ V : 4 key16 steps x 8 dim8 frags.
        const uint2* Vsf = (const uint2*)(asmem + ASMEM_V);
        #pragma unroll
        for (int c = 0; c < 4; c++) {
            uint32_t a[4];
            a[0] = Ps2[g * PSP + c * 8 + t];
            a[1] = Ps2[(g + 8) * PSP + c * 8 + t];
            a[2] = Ps2[g * PSP + c * 8 + t + 4];
            a[3] = Ps2[(g + 8) * PSP + c * 8 + t + 4];
            #pragma unroll
            for (int d = 0; d < 8; d++) {
                uint2 b = Vsf[((c * 8 + d) << 5) + lane];
                mma_f16(o[d], a, b.x, b.y);
            }
        }
        __syncwarp();
    }

    // Epilogue: O /= l -> half2 bounce -> g_yp in proj A-frag layout.
    float inv0 = 1.f / l0, inv1 = 1.f / l1;
    #pragma unroll
    for (int d = 0; d < 8; d++) {
        Ps2[g * PSP + 4*d + t]       = h2pk(o[d][0] * inv0, o[d][1] * inv0);
        Ps2[(g + 8) * PSP + 4*d + t] = h2pk(o[d][2] * inv1, o[d][3] * inv1);
    }
    __syncwarp();

    const int b = bh / Hn, h = bh % Hn;
    const int m16 = (b * Tn + qbase + wid * 16) >> 4;
    uint4* yp4 = (uint4*)g_yp;
    #pragma unroll
    for (int k = 0; k < 4; k++) {
        uint4 v;
        v.x = Ps2[g * PSP + k * 8 + t];
        v.y = Ps2[(g + 8) * PSP + k * 8 + t];
        v.z = Ps2[g * PSP + k * 8 + t + 4];
        v.w = Ps2[(g + 8) * PSP + k * 8 + t + 4];
        yp4[(size_t)(m16 * 64 + h * 4 + k) * 32 + lane] = v;
    }
}

// ---------------------------------------------------------------------------
extern "C" void kernel_launch(void* const* d_in, const int* in_sizes, int n_in,
                              void* d_out, int out_size)
{
    const float* x      = (const float*)d_in[0];
    const float* w_attn = (const float*)d_in[1];
    const float* b_attn = (const float*)d_in[2];
    const float* w_proj = (const float*)d_in[3];
    const float* b_proj = (const float*)d_in[4];
    float* out = (float*)d_out;

    cudaFuncSetAttribute(gemm_pk<0>, cudaFuncAttributeMaxDynamicSharedMemorySize, GSMEM0_SZ);
    cudaFuncSetAttribute(gemm_pk<1>, cudaFuncAttributeMaxDynamicSharedMemorySize, GSMEM1_SZ);
    cudaFuncSetAttribute(attn_pk,    cudaFuncAttributeMaxDynamicSharedMemorySize, ASMEM_SZ);

    __half* xp; cudaGetSymbolAddress((void**)&xp, g_xp);
    __half* wt; cudaGetSymbolAddress((void**)&wt, g_wt);
    __half* wp; cudaGetSymbolAddress((void**)&wp, g_wp);

    // 0) Prep: pack x and weights into fp16 fragment layouts.
    pack_a<<<dim3(BTn / 16, Cn / 256), 256>>>(x, xp, Cn);
    pack_b<<<dim3(3 * Cn / 64, Cn / 64), 256>>>(w_attn, wt, Cn, 3 * Cn);
    pack_b<<<dim3(Cn / 64, Cn / 64), 256>>>(w_proj, wp, Cn, Cn);

    // 1) QKV GEMM -> g_qp/g_kp/g_vp (attention fragment layouts, fused pack).
    {
        dim3 grid(3 * Cn / 128, BTn / 128);   // (24, 32)
        gemm_pk<0><<<grid, 128, GSMEM0_SZ>>>(wt, b_attn, nullptr, BTn, 3 * Cn, Cn);
    }
    // 2) Causal flash attention -> g_yp (proj A-frag layout, fused pack).
    {
        dim3 grid(Bn * Hn, Tn / 64);
        attn_pk<<<grid, 128, ASMEM_SZ>>>();
    }
    // 3) Projection GEMM: g_yp @ w_proj + b_proj -> out (fp32).
    {
        dim3 grid(Cn / 128, BTn / 128);       // (8, 32)
        gemm_pk<1><<<grid, 128, GSMEM1_SZ>>>(wp, b_proj, out, BTn, Cn, Cn);
    }
}